// round 1
// baseline (speedup 1.0000x reference)
#include <cuda_runtime.h>

#define NH    7
#define HD    128
#define BB    4
#define TT    2048
#define HID   896
#define MTOT  (BB*TT)   // 8192

// Scratch (allocation-free rule: __device__ globals)
__device__ float g_q[(size_t)NH * MTOT * HD];
__device__ float g_k[(size_t)NH * MTOT * HD];
__device__ float g_v[(size_t)NH * MTOT * HD];
__device__ float g_att[(size_t)MTOT * HID];

// ---------------------------------------------------------------------------
// QKV projection: for each (head, sel in {q,k,v}) compute
//   out[m, d] = sum_h X[m, h] * W[h, d],  M=8192, N=128, K=896
// 128-row M tile, full 128-col N tile, BK=16, 256 threads, 8x8 microtile.
// ---------------------------------------------------------------------------
__global__ void __launch_bounds__(256) proj_kernel(
    const float* __restrict__ x,
    const float* __restrict__ Wq,
    const float* __restrict__ Wk,
    const float* __restrict__ Wv)
{
    int z = blockIdx.y;                 // 0..20
    int head = z / 3, wsel = z - head * 3;
    const float* W = (wsel == 0 ? Wq : (wsel == 1 ? Wk : Wv)) + (size_t)head * HID * HD;
    float* out = (wsel == 0 ? g_q : (wsel == 1 ? g_k : g_v)) + (size_t)head * MTOT * HD;
    int m0 = blockIdx.x * 128;

    __shared__ float As[16][132];   // [kk][row], transposed
    __shared__ float Bs[16][132];   // [kk][col]

    int tid = threadIdx.x;
    int ty = tid >> 4, tx = tid & 15;

    float acc[8][8];
    #pragma unroll
    for (int i = 0; i < 8; i++)
        #pragma unroll
        for (int j = 0; j < 8; j++) acc[i][j] = 0.f;

    int ar = tid >> 2;              // 0..63
    int ak = (tid & 3) << 2;        // 0,4,8,12
    int bc = (tid & 31) << 2;       // 0..124
    int bk = tid >> 5;              // 0..7

    for (int k0 = 0; k0 < HID; k0 += 16) {
        #pragma unroll
        for (int rr = 0; rr < 2; rr++) {
            int row = ar + rr * 64;
            float4 a = *(const float4*)(x + (size_t)(m0 + row) * HID + k0 + ak);
            As[ak + 0][row] = a.x; As[ak + 1][row] = a.y;
            As[ak + 2][row] = a.z; As[ak + 3][row] = a.w;
        }
        #pragma unroll
        for (int kp = 0; kp < 2; kp++) {
            int kr = bk + kp * 8;
            *(float4*)&Bs[kr][bc] = *(const float4*)(W + (size_t)(k0 + kr) * HD + bc);
        }
        __syncthreads();
        #pragma unroll
        for (int kk = 0; kk < 16; kk++) {
            float4 a0 = *(float4*)&As[kk][ty * 8];
            float4 a1 = *(float4*)&As[kk][ty * 8 + 4];
            float4 b0 = *(float4*)&Bs[kk][tx * 4];
            float4 b1 = *(float4*)&Bs[kk][64 + tx * 4];
            float av[8] = {a0.x, a0.y, a0.z, a0.w, a1.x, a1.y, a1.z, a1.w};
            float bv[8] = {b0.x, b0.y, b0.z, b0.w, b1.x, b1.y, b1.z, b1.w};
            #pragma unroll
            for (int i = 0; i < 8; i++)
                #pragma unroll
                for (int j = 0; j < 8; j++) acc[i][j] += av[i] * bv[j];
        }
        __syncthreads();
    }
    #pragma unroll
    for (int i = 0; i < 8; i++) {
        float* op = out + (size_t)(m0 + ty * 8 + i) * HD;
        *(float4*)(op + tx * 4)      = make_float4(acc[i][0], acc[i][1], acc[i][2], acc[i][3]);
        *(float4*)(op + 64 + tx * 4) = make_float4(acc[i][4], acc[i][5], acc[i][6], acc[i][7]);
    }
}

// ---------------------------------------------------------------------------
// Masked flash attention, BM=BN=64, d=128, online softmax (exp2 space).
// Grid: (32 m-tiles, 4 batch, 7 heads). 256 threads: ty=row-group (4 rows),
// tx=col-group. Writes concatenated-head layout into g_att directly.
// ---------------------------------------------------------------------------
#define ATTN_SMEM ((64*132*2 + 64*68) * 4)

__global__ void __launch_bounds__(256) attn_kernel(const int* __restrict__ causal_p)
{
    int h = blockIdx.z, b = blockIdx.y, mt = blockIdx.x;
    int m0 = mt * 64;
    const float* Q = g_q + (size_t)(h * BB + b) * TT * HD;
    const float* K = g_k + (size_t)(h * BB + b) * TT * HD;
    const float* V = g_v + (size_t)(h * BB + b) * TT * HD;

    extern __shared__ float sm[];
    float* Qs = sm;                  // [64][132]
    float* Ks = sm + 64 * 132;       // [64][132]  (K tile, then reused for V)
    float* Ps = sm + 2 * 64 * 132;   // [64][68]

    int tid = threadIdx.x;
    int ty = tid >> 4, tx = tid & 15;
    int causal = *causal_p;
    unsigned lm = (1u << h) | (1u << ((h + 1) % 7)) | (1u << ((h + 3) % 7));

    // Load Q tile
    for (int i = tid; i < 64 * 32; i += 256) {
        int r = i >> 5, c4 = (i & 31) << 2;
        *(float4*)&Qs[r * 132 + c4] = *(const float4*)(Q + (size_t)(m0 + r) * HD + c4);
    }

    const float SCL = 0.08838834764831845f * 1.4426950408889634f; // 1/sqrt(128) * log2(e)
    float mrow[4], lrow[4], o[4][8];
    #pragma unroll
    for (int i = 0; i < 4; i++) {
        mrow[i] = -1e30f; lrow[i] = 0.f;
        #pragma unroll
        for (int c = 0; c < 8; c++) o[i][c] = 0.f;
    }

    int nt = causal ? (mt + 1) : (TT / 64);
    for (int n = 0; n < nt; n++) {
        int n0 = n * 64;
        __syncthreads();   // protect Ks (prev V) + first-iter Qs
        for (int i = tid; i < 64 * 32; i += 256) {
            int r = i >> 5, c4 = (i & 31) << 2;
            *(float4*)&Ks[r * 132 + c4] = *(const float4*)(K + (size_t)(n0 + r) * HD + c4);
        }
        __syncthreads();

        // S = scale * Q K^T  (4x4 per thread)
        float s[4][4];
        #pragma unroll
        for (int i = 0; i < 4; i++)
            #pragma unroll
            for (int j = 0; j < 4; j++) s[i][j] = 0.f;
        #pragma unroll 8
        for (int kk = 0; kk < 128; kk += 4) {
            float4 qv[4], kv[4];
            #pragma unroll
            for (int i = 0; i < 4; i++) qv[i] = *(float4*)&Qs[(ty * 4 + i) * 132 + kk];
            #pragma unroll
            for (int j = 0; j < 4; j++) kv[j] = *(float4*)&Ks[(tx * 4 + j) * 132 + kk];
            #pragma unroll
            for (int i = 0; i < 4; i++)
                #pragma unroll
                for (int j = 0; j < 4; j++)
                    s[i][j] += qv[i].x * kv[j].x + qv[i].y * kv[j].y +
                               qv[i].z * kv[j].z + qv[i].w * kv[j].w;
        }

        // Mask + online softmax per row
        #pragma unroll
        for (int i = 0; i < 4; i++) {
            int gi = m0 + ty * 4 + i;
            float rmax = -1e30f;
            #pragma unroll
            for (int j = 0; j < 4; j++) {
                int gj = n0 + tx * 4 + j;
                bool hit = (lm >> (gj % 7)) & 1u;
                bool ok;
                if (causal) ok = (gj <= gi) && (hit || gj >= gi - 16);
                else        ok = hit || (gj >= gi - 16 && gj <= gi + 16);
                float val = ok ? s[i][j] * SCL : -1e30f;
                s[i][j] = val;
                rmax = fmaxf(rmax, val);
            }
            #pragma unroll
            for (int d = 8; d >= 1; d >>= 1)
                rmax = fmaxf(rmax, __shfl_xor_sync(0xffffffffu, rmax, d));
            float mnew = fmaxf(mrow[i], rmax);
            float corr = exp2f(mrow[i] - mnew);
            mrow[i] = mnew;
            float p0 = exp2f(s[i][0] - mnew);
            float p1 = exp2f(s[i][1] - mnew);
            float p2 = exp2f(s[i][2] - mnew);
            float p3 = exp2f(s[i][3] - mnew);
            *(float4*)&Ps[(ty * 4 + i) * 68 + tx * 4] = make_float4(p0, p1, p2, p3);
            float rsum = p0 + p1 + p2 + p3;
            #pragma unroll
            for (int d = 8; d >= 1; d >>= 1)
                rsum += __shfl_xor_sync(0xffffffffu, rsum, d);
            lrow[i] = lrow[i] * corr + rsum;
            #pragma unroll
            for (int c = 0; c < 8; c++) o[i][c] *= corr;
        }

        __syncthreads();   // Ps written, Ks reads done -> load V over Ks
        for (int i = tid; i < 64 * 32; i += 256) {
            int r = i >> 5, c4 = (i & 31) << 2;
            *(float4*)&Ks[r * 132 + c4] = *(const float4*)(V + (size_t)(n0 + r) * HD + c4);
        }
        __syncthreads();

        // O += P @ V
        #pragma unroll 4
        for (int j = 0; j < 64; j++) {
            float p[4];
            #pragma unroll
            for (int i = 0; i < 4; i++) p[i] = Ps[(ty * 4 + i) * 68 + j];
            float4 v0 = *(float4*)&Ks[j * 132 + tx * 4];
            float4 v1 = *(float4*)&Ks[j * 132 + 64 + tx * 4];
            #pragma unroll
            for (int i = 0; i < 4; i++) {
                o[i][0] += p[i] * v0.x; o[i][1] += p[i] * v0.y;
                o[i][2] += p[i] * v0.z; o[i][3] += p[i] * v0.w;
                o[i][4] += p[i] * v1.x; o[i][5] += p[i] * v1.y;
                o[i][6] += p[i] * v1.z; o[i][7] += p[i] * v1.w;
            }
        }
    }

    // Epilogue: normalize and scatter into concatenated-head layout
    #pragma unroll
    for (int i = 0; i < 4; i++) {
        float inv = 1.f / lrow[i];
        float* op = g_att + (size_t)((size_t)b * TT + m0 + ty * 4 + i) * HID + h * HD;
        *(float4*)(op + tx * 4) =
            make_float4(o[i][0] * inv, o[i][1] * inv, o[i][2] * inv, o[i][3] * inv);
        *(float4*)(op + 64 + tx * 4) =
            make_float4(o[i][4] * inv, o[i][5] * inv, o[i][6] * inv, o[i][7] * inv);
    }
}

// ---------------------------------------------------------------------------
// Output projection: out[m, o] = sum_c g_att[m, c] * Wo[o, c]   (NT GEMM)
// M=8192, N=896, K=896. 128x128 tiles, BK=16, 256 threads, 8x8 microtile.
// ---------------------------------------------------------------------------
__global__ void __launch_bounds__(256) outproj_kernel(
    const float* __restrict__ Wo, float* __restrict__ out)
{
    int m0 = blockIdx.x * 128;
    int n0 = blockIdx.y * 128;

    __shared__ float As[16][132];
    __shared__ float Bs[16][132];

    int tid = threadIdx.x;
    int ty = tid >> 4, tx = tid & 15;

    float acc[8][8];
    #pragma unroll
    for (int i = 0; i < 8; i++)
        #pragma unroll
        for (int j = 0; j < 8; j++) acc[i][j] = 0.f;

    int ar = tid >> 2;
    int ak = (tid & 3) << 2;

    for (int k0 = 0; k0 < HID; k0 += 16) {
        #pragma unroll
        for (int rr = 0; rr < 2; rr++) {
            int row = ar + rr * 64;
            float4 a = *(const float4*)(g_att + (size_t)(m0 + row) * HID + k0 + ak);
            As[ak + 0][row] = a.x; As[ak + 1][row] = a.y;
            As[ak + 2][row] = a.z; As[ak + 3][row] = a.w;
            float4 w = *(const float4*)(Wo + (size_t)(n0 + row) * HID + k0 + ak);
            Bs[ak + 0][row] = w.x; Bs[ak + 1][row] = w.y;
            Bs[ak + 2][row] = w.z; Bs[ak + 3][row] = w.w;
        }
        __syncthreads();
        #pragma unroll
        for (int kk = 0; kk < 16; kk++) {
            float4 a0 = *(float4*)&As[kk][ty * 8];
            float4 a1 = *(float4*)&As[kk][ty * 8 + 4];
            float4 b0 = *(float4*)&Bs[kk][tx * 4];
            float4 b1 = *(float4*)&Bs[kk][64 + tx * 4];
            float av[8] = {a0.x, a0.y, a0.z, a0.w, a1.x, a1.y, a1.z, a1.w};
            float bv[8] = {b0.x, b0.y, b0.z, b0.w, b1.x, b1.y, b1.z, b1.w};
            #pragma unroll
            for (int i = 0; i < 8; i++)
                #pragma unroll
                for (int j = 0; j < 8; j++) acc[i][j] += av[i] * bv[j];
        }
        __syncthreads();
    }
    #pragma unroll
    for (int i = 0; i < 8; i++) {
        float* op = out + (size_t)(m0 + ty * 8 + i) * HID + n0;
        *(float4*)(op + tx * 4)      = make_float4(acc[i][0], acc[i][1], acc[i][2], acc[i][3]);
        *(float4*)(op + 64 + tx * 4) = make_float4(acc[i][4], acc[i][5], acc[i][6], acc[i][7]);
    }
}

// ---------------------------------------------------------------------------
extern "C" void kernel_launch(void* const* d_in, const int* in_sizes, int n_in,
                              void* d_out, int out_size)
{
    const float* x  = (const float*)d_in[0];
    const float* Wq = (const float*)d_in[1];
    const float* Wk = (const float*)d_in[2];
    const float* Wv = (const float*)d_in[3];
    const float* Wo = (const float*)d_in[4];
    const int* isc  = (const int*)d_in[5];
    float* out = (float*)d_out;

    cudaFuncSetAttribute(attn_kernel, cudaFuncAttributeMaxDynamicSharedMemorySize, ATTN_SMEM);

    proj_kernel<<<dim3(MTOT / 128, 21), 256>>>(x, Wq, Wk, Wv);
    attn_kernel<<<dim3(TT / 64, BB, NH), 256, ATTN_SMEM>>>(isc);
    outproj_kernel<<<dim3(MTOT / 128, HID / 128), 256>>>(Wo, out);
}

// round 3
// speedup vs baseline: 2.0645x; 2.0645x over previous
#include <cuda_runtime.h>

#define NH    7
#define HD    128
#define BB    4
#define TT    2048
#define HID   896
#define MTOT  (BB*TT)   // 8192

// Scratch (allocation-free rule: __device__ globals)
__device__ float g_q[(size_t)NH * MTOT * HD];
__device__ float g_k[(size_t)NH * MTOT * HD];
__device__ float g_v[(size_t)NH * MTOT * HD];
__device__ float g_att[(size_t)MTOT * HID];

// tf32 round-to-nearest (unbiased) — value kept as float bits with low 13 bits zero
__device__ __forceinline__ float f2tf(float x) {
    unsigned u;
    asm("cvt.rna.tf32.f32 %0, %1;" : "=r"(u) : "f"(x));
    return __uint_as_float(u);
}

__device__ __forceinline__ void mma8(float& d0, float& d1, float& d2, float& d3,
                                     unsigned a0, unsigned a1, unsigned a2, unsigned a3,
                                     unsigned b0, unsigned b1) {
    asm volatile(
        "mma.sync.aligned.m16n8k8.row.col.f32.tf32.tf32.f32 "
        "{%0,%1,%2,%3}, {%4,%5,%6,%7}, {%8,%9}, {%0,%1,%2,%3};\n"
        : "+f"(d0), "+f"(d1), "+f"(d2), "+f"(d3)
        : "r"(a0), "r"(a1), "r"(a2), "r"(a3), "r"(b0), "r"(b1));
}

// k-pair permutation within each 8-block: element k stored at position
// 2*(k&3) + ((k&7)>>2), so fragment pair (c, c+4) sits at (2c, 2c+1) -> LDS.64
__device__ __forceinline__ int kperm(int k) {
    int kl = k & 7;
    return (k & ~7) + 2 * (kl & 3) + (kl >> 2);
}

// ===========================================================================
// tf32 GEMM core: C[M,N] = A[M,K=896] * B(k,n).  CTA 256 thr, tile 128x128,
// BK=32, warp tile 32x64 (2 m-frags x 8 n-frags), k-pair-permuted smem.
// BKC=true:  B(k,n) = Bsrc[n*HID + k]  (k-contiguous rows; Wo)
// BKC=false: B(k,n) = Bsrc[k*HD + n]   (n-contiguous rows; Wq/Wk/Wv, N=128)
// ===========================================================================
#define GLD 36

template<bool BKC>
__device__ __forceinline__ void gemm_core(
    const float* __restrict__ A, const float* __restrict__ Bsrc,
    float* __restrict__ C, int ldc, int m0, int n0,
    float* As, float* Bs)
{
    int tid = threadIdx.x, lane = tid & 31, wid = tid >> 5;
    int wm = (wid >> 1) * 32, wn = (wid & 1) * 64;
    int r = lane >> 2, c = lane & 3;

    float acc[2][8][4];
    #pragma unroll
    for (int f = 0; f < 2; f++)
        #pragma unroll
        for (int nf = 0; nf < 8; nf++)
            #pragma unroll
            for (int e = 0; e < 4; e++) acc[f][nf][e] = 0.f;

    for (int k0 = 0; k0 < HID; k0 += 32) {
        // stage A: As[m][perm(k)] (tf32-rounded)
        #pragma unroll
        for (int j = 0; j < 4; j++) {
            int idx = tid + 256 * j;
            int m = idx >> 3, kq = idx & 7;
            float4 v = *(const float4*)(A + (size_t)(m0 + m) * HID + k0 + kq * 4);
            As[m * GLD + kperm(kq * 4 + 0)] = f2tf(v.x);
            As[m * GLD + kperm(kq * 4 + 1)] = f2tf(v.y);
            As[m * GLD + kperm(kq * 4 + 2)] = f2tf(v.z);
            As[m * GLD + kperm(kq * 4 + 3)] = f2tf(v.w);
        }
        // stage B: Bs[n][perm(k)]
        if (BKC) {
            #pragma unroll
            for (int j = 0; j < 4; j++) {
                int idx = tid + 256 * j;
                int n = idx >> 3, kq = idx & 7;
                float4 v = *(const float4*)(Bsrc + (size_t)(n0 + n) * HID + k0 + kq * 4);
                Bs[n * GLD + kperm(kq * 4 + 0)] = f2tf(v.x);
                Bs[n * GLD + kperm(kq * 4 + 1)] = f2tf(v.y);
                Bs[n * GLD + kperm(kq * 4 + 2)] = f2tf(v.z);
                Bs[n * GLD + kperm(kq * 4 + 3)] = f2tf(v.w);
            }
        } else {
            #pragma unroll
            for (int j = 0; j < 4; j++) {
                int idx = tid + 256 * j;
                int k = idx >> 5, nq = idx & 31;
                float4 v = *(const float4*)(Bsrc + (size_t)(k0 + k) * HD + nq * 4);
                int p = kperm(k);
                Bs[(nq * 4 + 0) * GLD + p] = f2tf(v.x);
                Bs[(nq * 4 + 1) * GLD + p] = f2tf(v.y);
                Bs[(nq * 4 + 2) * GLD + p] = f2tf(v.z);
                Bs[(nq * 4 + 3) * GLD + p] = f2tf(v.w);
            }
        }
        __syncthreads();

        #pragma unroll
        for (int ks = 0; ks < 4; ks++) {
            int kb = ks * 8 + 2 * c;
            unsigned a[2][4];
            #pragma unroll
            for (int f = 0; f < 2; f++) {
                int row = wm + f * 16 + r;
                uint2 lo = *(const uint2*)&As[row * GLD + kb];
                uint2 hi = *(const uint2*)&As[(row + 8) * GLD + kb];
                a[f][0] = lo.x; a[f][1] = hi.x; a[f][2] = lo.y; a[f][3] = hi.y;
            }
            #pragma unroll
            for (int nf = 0; nf < 8; nf++) {
                uint2 bb = *(const uint2*)&Bs[(wn + nf * 8 + r) * GLD + kb];
                mma8(acc[0][nf][0], acc[0][nf][1], acc[0][nf][2], acc[0][nf][3],
                     a[0][0], a[0][1], a[0][2], a[0][3], bb.x, bb.y);
                mma8(acc[1][nf][0], acc[1][nf][1], acc[1][nf][2], acc[1][nf][3],
                     a[1][0], a[1][1], a[1][2], a[1][3], bb.x, bb.y);
            }
        }
        __syncthreads();
    }

    #pragma unroll
    for (int f = 0; f < 2; f++) {
        int row = m0 + wm + f * 16 + r;
        #pragma unroll
        for (int nf = 0; nf < 8; nf++) {
            int col = n0 + wn + nf * 8 + 2 * c;
            *(float2*)&C[(size_t)row * ldc + col] =
                make_float2(acc[f][nf][0], acc[f][nf][1]);
            *(float2*)&C[(size_t)(row + 8) * ldc + col] =
                make_float2(acc[f][nf][2], acc[f][nf][3]);
        }
    }
}

__global__ void __launch_bounds__(256) proj_tc(
    const float* __restrict__ x, const float* __restrict__ Wq,
    const float* __restrict__ Wk, const float* __restrict__ Wv)
{
    __shared__ float As[128 * GLD];
    __shared__ float Bs[128 * GLD];
    int z = blockIdx.y;
    int head = z / 3, sel = z - head * 3;
    const float* W = (sel == 0 ? Wq : (sel == 1 ? Wk : Wv)) + (size_t)head * HID * HD;
    float* out = (sel == 0 ? g_q : (sel == 1 ? g_k : g_v)) + (size_t)head * MTOT * HD;
    gemm_core<false>(x, W, out, HD, blockIdx.x * 128, 0, As, Bs);
}

__global__ void __launch_bounds__(256) outproj_tc(
    const float* __restrict__ Wo, float* __restrict__ out)
{
    __shared__ float As[128 * GLD];
    __shared__ float Bs[128 * GLD];
    gemm_core<true>(g_att, Wo, out, HID, blockIdx.x * 128, blockIdx.y * 128, As, Bs);
}

// ===========================================================================
// Masked flash attention on tensor cores.  BM=64, BN=64, d=128, 128 threads
// (4 warps, each owns m16).  Q fragments in registers; K/V share one smem
// buffer (sequential use); V staged transposed [d][perm(s)]; P staged in
// fragment-permuted layout; online softmax on S fragments.
// ===========================================================================
#define KS_LD 132
#define V_LD  68
#define P_LD  68
#define KV_FLOATS 8704                   // max(64*132, 128*68)
#define ATTN_SM ((KV_FLOATS + 64 * P_LD) * 4)

__global__ void __launch_bounds__(128) attn_tc(const int* __restrict__ causal_p)
{
    extern __shared__ float sm[];
    float* KV = sm;
    float* Ps = sm + KV_FLOATS;

    int tid = threadIdx.x, lane = tid & 31, wid = tid >> 5;
    int h = blockIdx.z, b = blockIdx.y, mt = blockIdx.x;
    int m0 = mt * 64;
    const float* Q = g_q + (size_t)(h * BB + b) * TT * HD;
    const float* K = g_k + (size_t)(h * BB + b) * TT * HD;
    const float* V = g_v + (size_t)(h * BB + b) * TT * HD;
    int causal = *causal_p;
    unsigned lm = (1u << h) | (1u << ((h + 1) % 7)) | (1u << ((h + 3) % 7));

    int r = lane >> 2, c = lane & 3;
    int rowq = m0 + wid * 16 + r;          // global row (lo); hi = rowq+8
    int rloc = wid * 16 + r;
    // P store positions for S-frag cols 2c / 2c+1 within an 8-block
    int posE = 2 * ((2 * c) & 3) + ((2 * c) >> 2);
    int posO = 2 * ((2 * c + 1) & 3) + ((2 * c + 1) >> 2);

    // Q fragments in registers (one-time load, tf32-rounded)
    unsigned qf[16][4];
    #pragma unroll
    for (int kb = 0; kb < 16; kb++) {
        qf[kb][0] = __float_as_uint(f2tf(Q[(size_t)rowq * HD + kb * 8 + c]));
        qf[kb][1] = __float_as_uint(f2tf(Q[(size_t)(rowq + 8) * HD + kb * 8 + c]));
        qf[kb][2] = __float_as_uint(f2tf(Q[(size_t)rowq * HD + kb * 8 + c + 4]));
        qf[kb][3] = __float_as_uint(f2tf(Q[(size_t)(rowq + 8) * HD + kb * 8 + c + 4]));
    }

    float o[16][4];
    #pragma unroll
    for (int nf = 0; nf < 16; nf++)
        #pragma unroll
        for (int e = 0; e < 4; e++) o[nf][e] = 0.f;
    float m_lo = -1e30f, m_hi = -1e30f, l_lo = 0.f, l_hi = 0.f;
    const float SCL = 0.08838834764831845f * 1.4426950408889634f; // 1/sqrt(128)*log2(e)

    int nt = causal ? (mt + 1) : (TT / 64);
    for (int n = 0; n < nt; n++) {
        int n0 = n * 64;
        __syncthreads();
        // stage K: KV[n][perm(k)], tf32
        #pragma unroll
        for (int j = 0; j < 16; j++) {
            int idx = tid + 128 * j;
            int nn = idx >> 5, kq = idx & 31;
            float4 v = *(const float4*)(K + (size_t)(n0 + nn) * HD + kq * 4);
            KV[nn * KS_LD + kperm(kq * 4 + 0)] = f2tf(v.x);
            KV[nn * KS_LD + kperm(kq * 4 + 1)] = f2tf(v.y);
            KV[nn * KS_LD + kperm(kq * 4 + 2)] = f2tf(v.z);
            KV[nn * KS_LD + kperm(kq * 4 + 3)] = f2tf(v.w);
        }
        __syncthreads();

        // S = Q K^T (fragments)
        float s[8][4];
        #pragma unroll
        for (int nf = 0; nf < 8; nf++)
            #pragma unroll
            for (int e = 0; e < 4; e++) s[nf][e] = 0.f;
        #pragma unroll
        for (int kb = 0; kb < 16; kb++) {
            #pragma unroll
            for (int nf = 0; nf < 8; nf++) {
                uint2 bb = *(const uint2*)&KV[(nf * 8 + r) * KS_LD + kb * 8 + 2 * c];
                mma8(s[nf][0], s[nf][1], s[nf][2], s[nf][3],
                     qf[kb][0], qf[kb][1], qf[kb][2], qf[kb][3], bb.x, bb.y);
            }
        }

        // mask + online softmax
        float mx_lo = -1e30f, mx_hi = -1e30f;
        #pragma unroll
        for (int nf = 0; nf < 8; nf++) {
            #pragma unroll
            for (int t = 0; t < 2; t++) {
                int gj = n0 + nf * 8 + 2 * c + t;
                int hit = (lm >> (gj % 7)) & 1;
                int gi_lo = rowq, gi_hi = rowq + 8;
                bool ok_lo, ok_hi;
                if (causal) {
                    ok_lo = (gj <= gi_lo) && (hit || gj >= gi_lo - 16);
                    ok_hi = (gj <= gi_hi) && (hit || gj >= gi_hi - 16);
                } else {
                    ok_lo = hit || (gj >= gi_lo - 16 && gj <= gi_lo + 16);
                    ok_hi = hit || (gj >= gi_hi - 16 && gj <= gi_hi + 16);
                }
                float vlo = ok_lo ? s[nf][t] * SCL : -1e30f;
                float vhi = ok_hi ? s[nf][2 + t] * SCL : -1e30f;
                s[nf][t] = vlo; s[nf][2 + t] = vhi;
                mx_lo = fmaxf(mx_lo, vlo); mx_hi = fmaxf(mx_hi, vhi);
            }
        }
        mx_lo = fmaxf(mx_lo, __shfl_xor_sync(0xffffffffu, mx_lo, 1));
        mx_lo = fmaxf(mx_lo, __shfl_xor_sync(0xffffffffu, mx_lo, 2));
        mx_hi = fmaxf(mx_hi, __shfl_xor_sync(0xffffffffu, mx_hi, 1));
        mx_hi = fmaxf(mx_hi, __shfl_xor_sync(0xffffffffu, mx_hi, 2));

        float mn_lo = fmaxf(m_lo, mx_lo), mn_hi = fmaxf(m_hi, mx_hi);
        float cor_lo = exp2f(m_lo - mn_lo), cor_hi = exp2f(m_hi - mn_hi);
        m_lo = mn_lo; m_hi = mn_hi;

        float sum_lo = 0.f, sum_hi = 0.f;
        #pragma unroll
        for (int nf = 0; nf < 8; nf++) {
            float p0 = exp2f(s[nf][0] - mn_lo);
            float p1 = exp2f(s[nf][1] - mn_lo);
            float p2 = exp2f(s[nf][2] - mn_hi);
            float p3 = exp2f(s[nf][3] - mn_hi);
            sum_lo += p0 + p1; sum_hi += p2 + p3;
            Ps[rloc * P_LD + nf * 8 + posE] = f2tf(p0);
            Ps[rloc * P_LD + nf * 8 + posO] = f2tf(p1);
            Ps[(rloc + 8) * P_LD + nf * 8 + posE] = f2tf(p2);
            Ps[(rloc + 8) * P_LD + nf * 8 + posO] = f2tf(p3);
        }
        sum_lo += __shfl_xor_sync(0xffffffffu, sum_lo, 1);
        sum_lo += __shfl_xor_sync(0xffffffffu, sum_lo, 2);
        sum_hi += __shfl_xor_sync(0xffffffffu, sum_hi, 1);
        sum_hi += __shfl_xor_sync(0xffffffffu, sum_hi, 2);
        l_lo = l_lo * cor_lo + sum_lo;
        l_hi = l_hi * cor_hi + sum_hi;
        #pragma unroll
        for (int nf = 0; nf < 16; nf++) {
            o[nf][0] *= cor_lo; o[nf][1] *= cor_lo;
            o[nf][2] *= cor_hi; o[nf][3] *= cor_hi;
        }

        __syncthreads();   // K reads done, Ps written -> stage V over KV
        // stage V transposed: KV[d][perm(s)]   (ss = lane-varying for
        // conflict-free STS; gmem reads uncoalesced but L1-reused)
        #pragma unroll
        for (int j = 0; j < 16; j++) {
            int idx = tid + 128 * j;
            int ss = idx & 63, dq = idx >> 6;
            float4 v = *(const float4*)(V + (size_t)(n0 + ss) * HD + dq * 4);
            int ps = kperm(ss);
            KV[(dq * 4 + 0) * V_LD + ps] = f2tf(v.x);
            KV[(dq * 4 + 1) * V_LD + ps] = f2tf(v.y);
            KV[(dq * 4 + 2) * V_LD + ps] = f2tf(v.z);
            KV[(dq * 4 + 3) * V_LD + ps] = f2tf(v.w);
        }
        __syncthreads();

        // O += P @ V
        #pragma unroll
        for (int kb = 0; kb < 8; kb++) {
            uint2 plo = *(const uint2*)&Ps[rloc * P_LD + kb * 8 + 2 * c];
            uint2 phi = *(const uint2*)&Ps[(rloc + 8) * P_LD + kb * 8 + 2 * c];
            #pragma unroll
            for (int nf = 0; nf < 16; nf++) {
                uint2 bb = *(const uint2*)&KV[(nf * 8 + r) * V_LD + kb * 8 + 2 * c];
                mma8(o[nf][0], o[nf][1], o[nf][2], o[nf][3],
                     plo.x, phi.x, plo.y, phi.y, bb.x, bb.y);
            }
        }
    }

    // epilogue: normalize, write concatenated-head layout
    float inv_lo = 1.f / l_lo, inv_hi = 1.f / l_hi;
    float* OPl = g_att + ((size_t)b * TT + rowq) * HID + h * HD;
    float* OPh = g_att + ((size_t)b * TT + rowq + 8) * HID + h * HD;
    #pragma unroll
    for (int nf = 0; nf < 16; nf++) {
        int d = nf * 8 + 2 * c;
        *(float2*)&OPl[d] = make_float2(o[nf][0] * inv_lo, o[nf][1] * inv_lo);
        *(float2*)&OPh[d] = make_float2(o[nf][2] * inv_hi, o[nf][3] * inv_hi);
    }
}

// ---------------------------------------------------------------------------
extern "C" void kernel_launch(void* const* d_in, const int* in_sizes, int n_in,
                              void* d_out, int out_size)
{
    const float* x  = (const float*)d_in[0];
    const float* Wq = (const float*)d_in[1];
    const float* Wk = (const float*)d_in[2];
    const float* Wv = (const float*)d_in[3];
    const float* Wo = (const float*)d_in[4];
    const int* isc  = (const int*)d_in[5];
    float* out = (float*)d_out;

    cudaFuncSetAttribute(attn_tc, cudaFuncAttributeMaxDynamicSharedMemorySize, ATTN_SM);

    proj_tc<<<dim3(MTOT / 128, 21), 256>>>(x, Wq, Wk, Wv);
    attn_tc<<<dim3(TT / 64, BB, NH), 128, ATTN_SM>>>(isc);
    outproj_tc<<<dim3(MTOT / 128, HID / 128), 256>>>(Wo, out);
}

// round 4
// speedup vs baseline: 3.2762x; 1.5869x over previous
#include <cuda_runtime.h>

#define NH    7
#define HD    128
#define BB    4
#define TT    2048
#define HID   896
#define MTOT  (BB*TT)   // 8192
#define CPAD  896       // padded compact length (>= max 879, multiple of 64)

// Scratch (allocation-free rule: __device__ globals)
__device__ float g_xt[(size_t)MTOT * HID];            // x, tf32-rounded, k-permuted
__device__ float g_wt[(size_t)21 * HD * HID];         // W q/k/v transposed+rounded+perm
__device__ float g_wot[(size_t)HID * HID];            // Wo rounded+perm
__device__ float g_q[(size_t)NH * MTOT * HD];         // rounded, d-permuted
__device__ float g_k[(size_t)NH * MTOT * HD];
__device__ float g_v[(size_t)NH * MTOT * HD];
__device__ float g_kc[(size_t)NH * BB * CPAD * HD];   // Fano-compacted K
__device__ float g_vc[(size_t)NH * BB * CPAD * HD];
__device__ float g_att[(size_t)MTOT * HID];           // rounded, permuted

__device__ __forceinline__ float f2tf(float x) {
    unsigned u;
    asm("cvt.rna.tf32.f32 %0, %1;" : "=r"(u) : "f"(x));
    return __uint_as_float(u);
}

__device__ __forceinline__ void mma8(float& d0, float& d1, float& d2, float& d3,
                                     unsigned a0, unsigned a1, unsigned a2, unsigned a3,
                                     unsigned b0, unsigned b1) {
    asm volatile(
        "mma.sync.aligned.m16n8k8.row.col.f32.tf32.tf32.f32 "
        "{%0,%1,%2,%3}, {%4,%5,%6,%7}, {%8,%9}, {%0,%1,%2,%3};\n"
        : "+f"(d0), "+f"(d1), "+f"(d2), "+f"(d3)
        : "r"(a0), "r"(a1), "r"(a2), "r"(a3), "r"(b0), "r"(b1));
}

__device__ __forceinline__ int kperm(int k) {   // element k -> stored position
    int kl = k & 7;
    return (k & ~7) + 2 * (kl & 3) + (kl >> 2);
}

__device__ __forceinline__ void cp16(void* dst, const void* src) {
    unsigned d = (unsigned)__cvta_generic_to_shared(dst);
    asm volatile("cp.async.cg.shared.global [%0], [%1], 16;" :: "r"(d), "l"(src));
}
__device__ __forceinline__ void cp_commit() { asm volatile("cp.async.commit_group;"); }
template<int N> __device__ __forceinline__ void cp_wait() {
    asm volatile("cp.async.wait_group %0;" :: "n"(N));
}

// ===========================================================================
// Prep kernels: round to tf32 + permute k within 8-blocks (stored pos p holds
// element k = (p&~7) + ((p>>1)&3) + 4*(p&1))
// ===========================================================================
__global__ void prep_perm(const float* __restrict__ src, float* __restrict__ dst, int total8)
{
    int t = blockIdx.x * 256 + threadIdx.x;
    if (t >= total8) return;
    const float4* s = (const float4*)(src + (size_t)t * 8);
    float4 a = s[0], b = s[1];
    float4* d = (float4*)(dst + (size_t)t * 8);
    d[0] = make_float4(f2tf(a.x), f2tf(b.x), f2tf(a.y), f2tf(b.y));
    d[1] = make_float4(f2tf(a.z), f2tf(b.z), f2tf(a.w), f2tf(b.w));
}

// W[h][896][128] -> g_wt[z=3h+sel][n][896] (transposed, rounded, k-permuted)
__global__ void prep_wt(const float* __restrict__ Wq, const float* __restrict__ Wk,
                        const float* __restrict__ Wv)
{
    __shared__ float tb[32][33];
    int z = blockIdx.z, h = z / 3, sel = z % 3;
    const float* W = (sel == 0 ? Wq : (sel == 1 ? Wk : Wv)) + (size_t)h * HID * HD;
    int k0 = blockIdx.x * 32, n0 = blockIdx.y * 32;
    int tx = threadIdx.x, ty = threadIdx.y;
    #pragma unroll
    for (int i = 0; i < 4; i++)
        tb[ty + 8 * i][tx] = W[(size_t)(k0 + ty + 8 * i) * HD + n0 + tx];
    __syncthreads();
    int kl = (tx & ~7) + ((tx >> 1) & 3) + 4 * (tx & 1);   // inverse perm
    #pragma unroll
    for (int i = 0; i < 4; i++) {
        int n = n0 + ty + 8 * i;
        g_wt[((size_t)z * HD + n) * HID + k0 + tx] = f2tf(tb[kl][ty + 8 * i]);
    }
}

// ===========================================================================
// Fano compaction: gather line columns of K,V into dense arrays, zero padding
// ===========================================================================
__global__ void __launch_bounds__(256) compact_kv()
{
    int h = blockIdx.y >> 2, b = blockIdx.y & 3;
    int tid = threadIdx.x;
    int c = blockIdx.x * 64 + (tid >> 2);
    int seg = tid & 3;
    int s0 = h, s1 = (h + 1) % 7, s2 = (h + 3) % 7, t;
    if (s0 > s1) { t = s0; s0 = s1; s1 = t; }
    if (s1 > s2) { t = s1; s1 = s2; s2 = t; }
    if (s0 > s1) { t = s0; s0 = s1; s1 = t; }
    int cnt = 3 * 292 + (s0 < 4) + (s1 < 4) + (s2 < 4);
    int q = c / 3, u = c - 3 * q;
    int sl = (u == 0) ? s0 : ((u == 1) ? s1 : s2);
    int o = 7 * q + sl;
    bool valid = c < cnt;
    size_t sb = ((size_t)(h * BB + b) * TT + o) * HD + seg * 32;
    size_t db = ((size_t)(h * BB + b) * CPAD + c) * HD + seg * 32;
    float4 z4 = make_float4(0.f, 0.f, 0.f, 0.f);
    #pragma unroll
    for (int i = 0; i < 8; i++) {
        *(float4*)&g_kc[db + i * 4] = valid ? *(const float4*)&g_k[sb + i * 4] : z4;
        *(float4*)&g_vc[db + i * 4] = valid ? *(const float4*)&g_v[sb + i * 4] : z4;
    }
}

// ===========================================================================
// tf32 GEMM core: 128x128 CTA tile, BK=32, 8 warps (32x64), 3-stage cp.async
// ring, one sync/iter.  A,B pre-rounded+permuted in gmem, K-stride HID.
// ===========================================================================
#define GLD 36
#define GSTG (128 * GLD)                 // floats per (A or B) stage
#define GSMEM (3 * 2 * GSTG * 4)         // 110592 B

__device__ __forceinline__ void gemm_issue(const float* __restrict__ A,
                                           const float* __restrict__ B,
                                           float* As, float* Bs,
                                           int kb, int m0, int n0, int tid)
{
    #pragma unroll
    for (int j = 0; j < 4; j++) {
        int idx = tid + 256 * j;
        int row = idx >> 3, ch = idx & 7;
        cp16(As + row * GLD + ch * 4, A + (size_t)(m0 + row) * HID + kb * 32 + ch * 4);
    }
    #pragma unroll
    for (int j = 0; j < 4; j++) {
        int idx = tid + 256 * j;
        int row = idx >> 3, ch = idx & 7;
        cp16(Bs + row * GLD + ch * 4, B + (size_t)(n0 + row) * HID + kb * 32 + ch * 4);
    }
    cp_commit();
}

template<bool PERM>
__device__ __forceinline__ void gemm_main(const float* __restrict__ A,
                                          const float* __restrict__ B,
                                          float* __restrict__ C, int ldc,
                                          int m0, int n0)
{
    extern __shared__ float sg[];
    int tid = threadIdx.x, lane = tid & 31, wid = tid >> 5;
    int wm = (wid >> 1) * 32, wn = (wid & 1) * 64;
    int r = lane >> 2, lc = lane & 3;

    float acc[2][8][4];
    #pragma unroll
    for (int f = 0; f < 2; f++)
        #pragma unroll
        for (int nf = 0; nf < 8; nf++)
            #pragma unroll
            for (int e = 0; e < 4; e++) acc[f][nf][e] = 0.f;

    gemm_issue(A, B, sg, sg + GSTG, 0, m0, n0, tid);
    gemm_issue(A, B, sg + 2 * GSTG, sg + 3 * GSTG, 1, m0, n0, tid);

    #pragma unroll 1
    for (int kb = 0; kb < 28; kb++) {
        int st = kb % 3;
        float* As = sg + st * 2 * GSTG;
        float* Bs = As + GSTG;
        cp_wait<1>();
        __syncthreads();
        #pragma unroll
        for (int ks = 0; ks < 4; ks++) {
            int ko = ks * 8 + 2 * lc;
            unsigned a[2][4];
            #pragma unroll
            for (int f = 0; f < 2; f++) {
                int row = wm + f * 16 + r;
                uint2 lo = *(const uint2*)&As[row * GLD + ko];
                uint2 hi = *(const uint2*)&As[(row + 8) * GLD + ko];
                a[f][0] = lo.x; a[f][1] = hi.x; a[f][2] = lo.y; a[f][3] = hi.y;
            }
            #pragma unroll
            for (int nf = 0; nf < 8; nf++) {
                uint2 bb = *(const uint2*)&Bs[(wn + nf * 8 + r) * GLD + ko];
                mma8(acc[0][nf][0], acc[0][nf][1], acc[0][nf][2], acc[0][nf][3],
                     a[0][0], a[0][1], a[0][2], a[0][3], bb.x, bb.y);
                mma8(acc[1][nf][0], acc[1][nf][1], acc[1][nf][2], acc[1][nf][3],
                     a[1][0], a[1][1], a[1][2], a[1][3], bb.x, bb.y);
            }
        }
        if (kb + 2 < 28) {
            int ns = (kb + 2) % 3;
            gemm_issue(A, B, sg + ns * 2 * GSTG, sg + ns * 2 * GSTG + GSTG,
                       kb + 2, m0, n0, tid);
        } else {
            cp_commit();
        }
    }

    int posE = (lc < 2) ? 4 * lc : 4 * lc - 7;       // kperm(2lc)
    int posO = (lc < 2) ? 4 * lc + 2 : 4 * lc - 5;   // kperm(2lc+1)
    #pragma unroll
    for (int f = 0; f < 2; f++) {
        int row = m0 + wm + f * 16 + r;
        #pragma unroll
        for (int nf = 0; nf < 8; nf++) {
            int cb = n0 + wn + nf * 8;
            if (PERM) {
                C[(size_t)row * ldc + cb + posE] = f2tf(acc[f][nf][0]);
                C[(size_t)row * ldc + cb + posO] = f2tf(acc[f][nf][1]);
                C[(size_t)(row + 8) * ldc + cb + posE] = f2tf(acc[f][nf][2]);
                C[(size_t)(row + 8) * ldc + cb + posO] = f2tf(acc[f][nf][3]);
            } else {
                *(float2*)&C[(size_t)row * ldc + cb + 2 * lc] =
                    make_float2(acc[f][nf][0], acc[f][nf][1]);
                *(float2*)&C[(size_t)(row + 8) * ldc + cb + 2 * lc] =
                    make_float2(acc[f][nf][2], acc[f][nf][3]);
            }
        }
    }
}

__global__ void __launch_bounds__(256, 2) proj_tc()
{
    int z = blockIdx.y;
    float* out = ((z % 3) == 0 ? g_q : ((z % 3) == 1 ? g_k : g_v)) + (size_t)(z / 3) * MTOT * HD;
    gemm_main<true>(g_xt, g_wt + (size_t)z * HD * HID, out, HD, blockIdx.x * 128, 0);
}

__global__ void __launch_bounds__(256, 2) outproj_tc(float* __restrict__ out)
{
    gemm_main<false>(g_att, g_wot, out, HID, blockIdx.x * 128, blockIdx.y * 128);
}

// ===========================================================================
// Flash attention with Fano compaction + diagonal band.  BM=64, BN=64, d=128,
// 128 threads.  Compact tiles read g_kc/g_vc (cp.async copies, pre-rounded,
// pre-permuted); 2 band tiles read g_k/g_v with bounds-checked rows.
// ===========================================================================
#define KS_LD 132
#define V_LD  68
#define P_LD  68
#define KV_FLOATS 8704
#define ATTN_SM ((KV_FLOATS + 64 * P_LD) * 4)

__global__ void __launch_bounds__(128) attn_tc(const int* __restrict__ causal_p)
{
    extern __shared__ float sm[];
    float* KV = sm;
    float* Ps = sm + KV_FLOATS;

    int tid = threadIdx.x, lane = tid & 31, wid = tid >> 5;
    int h = blockIdx.z, b = blockIdx.y, mt = blockIdx.x;
    int m0 = mt * 64;
    size_t base = (size_t)(h * BB + b);
    const float* Q  = g_q + base * TT * HD;
    const float* Kf = g_k + base * TT * HD;
    const float* Vf = g_v + base * TT * HD;
    const float* Kc = g_kc + base * CPAD * HD;
    const float* Vc = g_vc + base * CPAD * HD;
    int causal = *causal_p;

    int s0 = h, s1 = (h + 1) % 7, s2 = (h + 3) % 7, tswp;
    if (s0 > s1) { tswp = s0; s0 = s1; s1 = tswp; }
    if (s1 > s2) { tswp = s1; s1 = s2; s2 = tswp; }
    if (s0 > s1) { tswp = s0; s0 = s1; s1 = tswp; }

    int r = lane >> 2, lc = lane & 3;
    int rowq = m0 + wid * 16 + r;
    int rloc = wid * 16 + r;
    int posE = (lc < 2) ? 4 * lc : 4 * lc - 7;
    int posO = (lc < 2) ? 4 * lc + 2 : 4 * lc - 5;

    // Q fragments (pre-rounded, permuted gmem -> adjacent pairs)
    unsigned qf[16][4];
    #pragma unroll
    for (int kb = 0; kb < 16; kb++) {
        float2 qlo = *(const float2*)(Q + (size_t)rowq * HD + kb * 8 + 2 * lc);
        float2 qhi = *(const float2*)(Q + (size_t)(rowq + 8) * HD + kb * 8 + 2 * lc);
        qf[kb][0] = __float_as_uint(qlo.x); qf[kb][1] = __float_as_uint(qhi.x);
        qf[kb][2] = __float_as_uint(qlo.y); qf[kb][3] = __float_as_uint(qhi.y);
    }

    float o[16][4];
    #pragma unroll
    for (int nf = 0; nf < 16; nf++)
        #pragma unroll
        for (int e = 0; e < 4; e++) o[nf][e] = 0.f;
    float m_lo = -1e30f, m_hi = -1e30f, l_lo = 0.f, l_hi = 0.f;
    const float SCL = 0.08838834764831845f * 1.4426950408889634f;

    int nt_c;
    if (causal) {
        int x = m0 + 47;
        int qq = x / 7, rr = x % 7;
        int bound = 3 * qq + (s0 < rr) + (s1 < rr) + (s2 < rr);
        nt_c = (bound + 63) >> 6;
    } else {
        nt_c = CPAD / 64;
    }
    int ntot = nt_c + 2;

    for (int n = 0; n < ntot; n++) {
        bool cmp = n < nt_c;
        int n0 = cmp ? n * 64 : 0;
        int bstart = m0 - 16 + (n - nt_c) * 64;

        __syncthreads();
        if (cmp) {
            #pragma unroll
            for (int j = 0; j < 16; j++) {
                int idx = tid + 128 * j;
                int nn = idx >> 5, ch = idx & 31;
                cp16(&KV[nn * KS_LD + ch * 4], Kc + (size_t)(n0 + nn) * HD + ch * 4);
            }
            cp_commit();
            cp_wait<0>();
        } else {
            #pragma unroll
            for (int j = 0; j < 16; j++) {
                int idx = tid + 128 * j;
                int nn = idx >> 5, ch = idx & 31;
                int og = bstart + nn;
                float4 v = (og >= 0 && og < TT)
                    ? *(const float4*)(Kf + (size_t)og * HD + ch * 4)
                    : make_float4(0.f, 0.f, 0.f, 0.f);
                *(float4*)&KV[nn * KS_LD + ch * 4] = v;
            }
        }
        __syncthreads();

        // S = Q K^T
        float s[8][4];
        #pragma unroll
        for (int nf = 0; nf < 8; nf++)
            #pragma unroll
            for (int e = 0; e < 4; e++) s[nf][e] = 0.f;
        #pragma unroll
        for (int kb = 0; kb < 16; kb++) {
            #pragma unroll
            for (int nf = 0; nf < 8; nf++) {
                uint2 bb = *(const uint2*)&KV[(nf * 8 + r) * KS_LD + kb * 8 + 2 * lc];
                mma8(s[nf][0], s[nf][1], s[nf][2], s[nf][3],
                     qf[kb][0], qf[kb][1], qf[kb][2], qf[kb][3], bb.x, bb.y);
            }
        }

        // mask + online softmax
        float mx_lo = -1e30f, mx_hi = -1e30f;
        int gi_lo = rowq, gi_hi = rowq + 8;
        #pragma unroll
        for (int nf = 0; nf < 8; nf++) {
            #pragma unroll
            for (int t = 0; t < 2; t++) {
                int cj = n0 + nf * 8 + 2 * lc + t;
                int og;
                if (cmp) {
                    int qq = cj / 3, uu = cj - 3 * qq;
                    int sl = (uu == 0) ? s0 : ((uu == 1) ? s1 : s2);
                    og = 7 * qq + sl;
                } else {
                    og = bstart + nf * 8 + 2 * lc + t;
                }
                bool ok_lo, ok_hi;
                if (cmp) {
                    if (causal) { ok_lo = og <= gi_lo - 17; ok_hi = og <= gi_hi - 17; }
                    else {
                        bool inr = og < TT;
                        ok_lo = inr && (og <= gi_lo - 17 || og >= gi_lo + 17);
                        ok_hi = inr && (og <= gi_hi - 17 || og >= gi_hi + 17);
                    }
                } else {
                    if (causal) {
                        ok_lo = (og >= gi_lo - 16) && (og <= gi_lo) && (og >= 0);
                        ok_hi = (og >= gi_hi - 16) && (og <= gi_hi) && (og >= 0);
                    } else {
                        bool inr = (og >= 0) && (og < TT);
                        ok_lo = inr && (og >= gi_lo - 16) && (og <= gi_lo + 16);
                        ok_hi = inr && (og >= gi_hi - 16) && (og <= gi_hi + 16);
                    }
                }
                float vlo = ok_lo ? s[nf][t] * SCL : -1e30f;
                float vhi = ok_hi ? s[nf][2 + t] * SCL : -1e30f;
                s[nf][t] = vlo; s[nf][2 + t] = vhi;
                mx_lo = fmaxf(mx_lo, vlo); mx_hi = fmaxf(mx_hi, vhi);
            }
        }
        mx_lo = fmaxf(mx_lo, __shfl_xor_sync(0xffffffffu, mx_lo, 1));
        mx_lo = fmaxf(mx_lo, __shfl_xor_sync(0xffffffffu, mx_lo, 2));
        mx_hi = fmaxf(mx_hi, __shfl_xor_sync(0xffffffffu, mx_hi, 1));
        mx_hi = fmaxf(mx_hi, __shfl_xor_sync(0xffffffffu, mx_hi, 2));

        float mn_lo = fmaxf(fmaxf(m_lo, mx_lo), -1e28f);
        float mn_hi = fmaxf(fmaxf(m_hi, mx_hi), -1e28f);
        float cor_lo = exp2f(m_lo - mn_lo), cor_hi = exp2f(m_hi - mn_hi);
        m_lo = mn_lo; m_hi = mn_hi;

        float sum_lo = 0.f, sum_hi = 0.f;
        #pragma unroll
        for (int nf = 0; nf < 8; nf++) {
            float p0 = exp2f(s[nf][0] - mn_lo);
            float p1 = exp2f(s[nf][1] - mn_lo);
            float p2 = exp2f(s[nf][2] - mn_hi);
            float p3 = exp2f(s[nf][3] - mn_hi);
            sum_lo += p0 + p1; sum_hi += p2 + p3;
            Ps[rloc * P_LD + nf * 8 + posE] = f2tf(p0);
            Ps[rloc * P_LD + nf * 8 + posO] = f2tf(p1);
            Ps[(rloc + 8) * P_LD + nf * 8 + posE] = f2tf(p2);
            Ps[(rloc + 8) * P_LD + nf * 8 + posO] = f2tf(p3);
        }
        sum_lo += __shfl_xor_sync(0xffffffffu, sum_lo, 1);
        sum_lo += __shfl_xor_sync(0xffffffffu, sum_lo, 2);
        sum_hi += __shfl_xor_sync(0xffffffffu, sum_hi, 1);
        sum_hi += __shfl_xor_sync(0xffffffffu, sum_hi, 2);
        l_lo = l_lo * cor_lo + sum_lo;
        l_hi = l_hi * cor_hi + sum_hi;
        #pragma unroll
        for (int nf = 0; nf < 16; nf++) {
            o[nf][0] *= cor_lo; o[nf][1] *= cor_lo;
            o[nf][2] *= cor_hi; o[nf][3] *= cor_hi;
        }

        __syncthreads();
        // stage V transposed: KV[d][perm(s)]; source is d-permuted, so the
        // float4 at quad dq holds d = {base,base+4,base+1,base+5} (dq even)
        // or {base+2,base+6,base+3,base+7} (dq odd), base = (dq>>1)*8.
        #pragma unroll
        for (int j = 0; j < 16; j++) {
            int idx = tid + 128 * j;
            int ss = idx & 63, dq = idx >> 6;
            float4 v;
            if (cmp) {
                v = *(const float4*)(Vc + (size_t)(n0 + ss) * HD + dq * 4);
            } else {
                int og = bstart + ss;
                v = (og >= 0 && og < TT)
                    ? *(const float4*)(Vf + (size_t)og * HD + dq * 4)
                    : make_float4(0.f, 0.f, 0.f, 0.f);
            }
            int ps = kperm(ss);
            int bse = (dq >> 1) * 8 + ((dq & 1) ? 2 : 0);
            KV[(bse + 0) * V_LD + ps] = v.x;
            KV[(bse + 4) * V_LD + ps] = v.y;
            KV[(bse + 1) * V_LD + ps] = v.z;
            KV[(bse + 5) * V_LD + ps] = v.w;
        }
        __syncthreads();

        // O += P @ V
        #pragma unroll
        for (int kb = 0; kb < 8; kb++) {
            uint2 plo = *(const uint2*)&Ps[rloc * P_LD + kb * 8 + 2 * lc];
            uint2 phi = *(const uint2*)&Ps[(rloc + 8) * P_LD + kb * 8 + 2 * lc];
            #pragma unroll
            for (int nf = 0; nf < 16; nf++) {
                uint2 bb = *(const uint2*)&KV[(nf * 8 + r) * V_LD + kb * 8 + 2 * lc];
                mma8(o[nf][0], o[nf][1], o[nf][2], o[nf][3],
                     plo.x, phi.x, plo.y, phi.y, bb.x, bb.y);
            }
        }
    }

    // epilogue: normalize, round, permuted concatenated-head layout
    float inv_lo = 1.f / l_lo, inv_hi = 1.f / l_hi;
    float* OPl = g_att + ((size_t)b * TT + rowq) * HID + h * HD;
    float* OPh = g_att + ((size_t)b * TT + rowq + 8) * HID + h * HD;
    #pragma unroll
    for (int nf = 0; nf < 16; nf++) {
        int cb = nf * 8;
        OPl[cb + posE] = f2tf(o[nf][0] * inv_lo);
        OPl[cb + posO] = f2tf(o[nf][1] * inv_lo);
        OPh[cb + posE] = f2tf(o[nf][2] * inv_hi);
        OPh[cb + posO] = f2tf(o[nf][3] * inv_hi);
    }
}

// ---------------------------------------------------------------------------
extern "C" void kernel_launch(void* const* d_in, const int* in_sizes, int n_in,
                              void* d_out, int out_size)
{
    const float* x  = (const float*)d_in[0];
    const float* Wq = (const float*)d_in[1];
    const float* Wk = (const float*)d_in[2];
    const float* Wv = (const float*)d_in[3];
    const float* Wo = (const float*)d_in[4];
    const int* isc  = (const int*)d_in[5];
    float* out = (float*)d_out;

    cudaFuncSetAttribute(proj_tc, cudaFuncAttributeMaxDynamicSharedMemorySize, GSMEM);
    cudaFuncSetAttribute(outproj_tc, cudaFuncAttributeMaxDynamicSharedMemorySize, GSMEM);
    cudaFuncSetAttribute(attn_tc, cudaFuncAttributeMaxDynamicSharedMemorySize, ATTN_SM);

    float* d_xt; cudaGetSymbolAddress((void**)&d_xt, g_xt);
    float* d_wot; cudaGetSymbolAddress((void**)&d_wot, g_wot);

    prep_perm<<<(MTOT * HID / 8 + 255) / 256, 256>>>(x, d_xt, MTOT * HID / 8);
    prep_perm<<<(HID * HID / 8 + 255) / 256, 256>>>(Wo, d_wot, HID * HID / 8);
    prep_wt<<<dim3(HID / 32, HD / 32, 21), dim3(32, 8)>>>(Wq, Wk, Wv);

    proj_tc<<<dim3(MTOT / 128, 21), 256, GSMEM>>>();
    compact_kv<<<dim3(CPAD / 64, NH * BB), 256>>>();
    attn_tc<<<dim3(TT / 64, BB, NH), 128, ATTN_SM>>>(isc);
    outproj_tc<<<dim3(MTOT / 128, HID / 128), 256, GSMEM>>>(out);
}

// round 6
// speedup vs baseline: 4.1278x; 1.2600x over previous
#include <cuda_runtime.h>

#define NH    7
#define HD    128
#define BB    4
#define TT    2048
#define HID   896
#define MTOT  (BB*TT)   // 8192
#define CPAD  896       // padded compact length (>= max 879, multiple of 64)

// Scratch (allocation-free rule: __device__ globals)
__device__ float g_xt[(size_t)MTOT * HID];            // x, tf32-rounded, k-permuted
__device__ float g_wt[(size_t)21 * HD * HID];         // W q/k/v transposed+rounded+perm
__device__ float g_wot[(size_t)HID * HID];            // Wo rounded+perm
__device__ float g_q[(size_t)NH * MTOT * HD];         // rounded, d-permuted
__device__ float g_k[(size_t)NH * MTOT * HD];
__device__ float g_v[(size_t)NH * MTOT * HD];
__device__ float g_kc[(size_t)NH * BB * CPAD * HD];   // Fano-compacted K [slot][d]
__device__ float g_vct[(size_t)NH * BB * HD * CPAD];  // compacted V^T [d][perm(slot)]
__device__ float g_att[(size_t)MTOT * HID];           // rounded, permuted

__device__ __forceinline__ float f2tf(float x) {
    unsigned u;
    asm("cvt.rna.tf32.f32 %0, %1;" : "=r"(u) : "f"(x));
    return __uint_as_float(u);
}

__device__ __forceinline__ void mma8(float& d0, float& d1, float& d2, float& d3,
                                     unsigned a0, unsigned a1, unsigned a2, unsigned a3,
                                     unsigned b0, unsigned b1) {
    asm volatile(
        "mma.sync.aligned.m16n8k8.row.col.f32.tf32.tf32.f32 "
        "{%0,%1,%2,%3}, {%4,%5,%6,%7}, {%8,%9}, {%0,%1,%2,%3};\n"
        : "+f"(d0), "+f"(d1), "+f"(d2), "+f"(d3)
        : "r"(a0), "r"(a1), "r"(a2), "r"(a3), "r"(b0), "r"(b1));
}

__device__ __forceinline__ int kperm(int k) {   // element k -> stored position
    int kl = k & 7;
    return (k & ~7) + 2 * (kl & 3) + (kl >> 2);
}

__device__ __forceinline__ void cp16(void* dst, const void* src) {
    unsigned d = (unsigned)__cvta_generic_to_shared(dst);
    asm volatile("cp.async.cg.shared.global [%0], [%1], 16;" :: "r"(d), "l"(src));
}
__device__ __forceinline__ void cp_commit() { asm volatile("cp.async.commit_group;"); }
template<int N> __device__ __forceinline__ void cp_wait() {
    asm volatile("cp.async.wait_group %0;" :: "n"(N));
}

// ===========================================================================
// Prep kernels
// ===========================================================================
__global__ void prep_perm(const float* __restrict__ src, float* __restrict__ dst, int total8)
{
    int t = blockIdx.x * 256 + threadIdx.x;
    if (t >= total8) return;
    const float4* s = (const float4*)(src + (size_t)t * 8);
    float4 a = s[0], b = s[1];
    float4* d = (float4*)(dst + (size_t)t * 8);
    d[0] = make_float4(f2tf(a.x), f2tf(b.x), f2tf(a.y), f2tf(b.y));
    d[1] = make_float4(f2tf(a.z), f2tf(b.z), f2tf(a.w), f2tf(b.w));
}

__global__ void prep_wt(const float* __restrict__ Wq, const float* __restrict__ Wk,
                        const float* __restrict__ Wv)
{
    __shared__ float tb[32][33];
    int z = blockIdx.z, h = z / 3, sel = z % 3;
    const float* W = (sel == 0 ? Wq : (sel == 1 ? Wk : Wv)) + (size_t)h * HID * HD;
    int k0 = blockIdx.x * 32, n0 = blockIdx.y * 32;
    int tx = threadIdx.x, ty = threadIdx.y;
    #pragma unroll
    for (int i = 0; i < 4; i++)
        tb[ty + 8 * i][tx] = W[(size_t)(k0 + ty + 8 * i) * HD + n0 + tx];
    __syncthreads();
    int kl = (tx & ~7) + ((tx >> 1) & 3) + 4 * (tx & 1);   // inverse perm
    #pragma unroll
    for (int i = 0; i < 4; i++) {
        int n = n0 + ty + 8 * i;
        g_wt[((size_t)z * HD + n) * HID + k0 + tx] = f2tf(tb[kl][ty + 8 * i]);
    }
}

__device__ __forceinline__ void fano_lines(int h, int& s0, int& s1, int& s2, int& cnt)
{
    int t;
    s0 = h; s1 = (h + 1) % 7; s2 = (h + 3) % 7;
    if (s0 > s1) { t = s0; s0 = s1; s1 = t; }
    if (s1 > s2) { t = s1; s1 = s2; s2 = t; }
    if (s0 > s1) { t = s0; s0 = s1; s1 = t; }
    cnt = 3 * 292 + (s0 < 4) + (s1 < 4) + (s2 < 4);
}

// K compaction: gather line columns into dense [slot][d]
__global__ void __launch_bounds__(256) compact_k()
{
    int h = blockIdx.y >> 2, b = blockIdx.y & 3;
    int tid = threadIdx.x;
    int c = blockIdx.x * 64 + (tid >> 2);
    int seg = tid & 3;
    int s0, s1, s2, cnt;
    fano_lines(h, s0, s1, s2, cnt);
    int q = c / 3, u = c - 3 * q;
    int sl = (u == 0) ? s0 : ((u == 1) ? s1 : s2);
    int o = 7 * q + sl;
    bool valid = c < cnt;
    size_t sb = ((size_t)(h * BB + b) * TT + o) * HD + seg * 32;
    size_t db = ((size_t)(h * BB + b) * CPAD + c) * HD + seg * 32;
    float4 z4 = make_float4(0.f, 0.f, 0.f, 0.f);
    #pragma unroll
    for (int i = 0; i < 8; i++)
        *(float4*)&g_kc[db + i * 4] = valid ? *(const float4*)&g_k[sb + i * 4] : z4;
}

// V compaction + transpose: g_vct[d_actual][kperm(slot)] = V[slot][d_actual]
// (source g_v is d-permuted storage; unpermute d during transpose)
__global__ void compact_vT()   // grid (CPAD/32, HD/32, 28), block (32, 8)
{
    __shared__ float tb[32][33];
    int z = blockIdx.z, h = z >> 2, b = z & 3;
    int s0, s1, s2, cnt;
    fano_lines(h, s0, s1, s2, cnt);
    int c0 = blockIdx.x * 32, d0 = blockIdx.y * 32;
    int tx = threadIdx.x, ty = threadIdx.y;
    size_t srcb = (size_t)(h * BB + b) * TT * HD;
    size_t dstb = (size_t)(h * BB + b) * HD * CPAD;
    // stored pos p holds actual element a(p)
    int al = (tx & ~24) >= 0 ? ((tx & ~7) + ((tx >> 1) & 3) + 4 * (tx & 1)) : 0;
    #pragma unroll
    for (int i = 0; i < 4; i++) {
        int c = c0 + ty + 8 * i;
        int q = c / 3, u = c - 3 * q;
        int sl = (u == 0) ? s0 : ((u == 1) ? s1 : s2);
        int og = 7 * q + sl;
        float val = (c < cnt) ? g_v[srcb + (size_t)og * HD + d0 + tx] : 0.f;
        tb[ty + 8 * i][al] = val;           // [c_local][actual d_local]
    }
    __syncthreads();
    int destc = c0 + (tx & ~7) + 2 * (tx & 3) + ((tx & 7) >> 2);  // kperm(c)
    #pragma unroll
    for (int i = 0; i < 4; i++) {
        int d = d0 + ty + 8 * i;
        g_vct[dstb + (size_t)d * CPAD + destc] = tb[tx][ty + 8 * i];
    }
}

// ===========================================================================
// tf32 GEMM core (unchanged from R4): 128x128 tile, BK=32, 3-stage cp.async
// ===========================================================================
#define GLD 36
#define GSTG (128 * GLD)
#define GSMEM (3 * 2 * GSTG * 4)

__device__ __forceinline__ void gemm_issue(const float* __restrict__ A,
                                           const float* __restrict__ B,
                                           float* As, float* Bs,
                                           int kb, int m0, int n0, int tid)
{
    #pragma unroll
    for (int j = 0; j < 4; j++) {
        int idx = tid + 256 * j;
        int row = idx >> 3, ch = idx & 7;
        cp16(As + row * GLD + ch * 4, A + (size_t)(m0 + row) * HID + kb * 32 + ch * 4);
    }
    #pragma unroll
    for (int j = 0; j < 4; j++) {
        int idx = tid + 256 * j;
        int row = idx >> 3, ch = idx & 7;
        cp16(Bs + row * GLD + ch * 4, B + (size_t)(n0 + row) * HID + kb * 32 + ch * 4);
    }
    cp_commit();
}

template<bool PERM>
__device__ __forceinline__ void gemm_main(const float* __restrict__ A,
                                          const float* __restrict__ B,
                                          float* __restrict__ C, int ldc,
                                          int m0, int n0)
{
    extern __shared__ float sg[];
    int tid = threadIdx.x, lane = tid & 31, wid = tid >> 5;
    int wm = (wid >> 1) * 32, wn = (wid & 1) * 64;
    int r = lane >> 2, lc = lane & 3;

    float acc[2][8][4];
    #pragma unroll
    for (int f = 0; f < 2; f++)
        #pragma unroll
        for (int nf = 0; nf < 8; nf++)
            #pragma unroll
            for (int e = 0; e < 4; e++) acc[f][nf][e] = 0.f;

    gemm_issue(A, B, sg, sg + GSTG, 0, m0, n0, tid);
    gemm_issue(A, B, sg + 2 * GSTG, sg + 3 * GSTG, 1, m0, n0, tid);

    #pragma unroll 1
    for (int kb = 0; kb < 28; kb++) {
        int st = kb % 3;
        float* As = sg + st * 2 * GSTG;
        float* Bs = As + GSTG;
        cp_wait<1>();
        __syncthreads();
        #pragma unroll
        for (int ks = 0; ks < 4; ks++) {
            int ko = ks * 8 + 2 * lc;
            unsigned a[2][4];
            #pragma unroll
            for (int f = 0; f < 2; f++) {
                int row = wm + f * 16 + r;
                uint2 lo = *(const uint2*)&As[row * GLD + ko];
                uint2 hi = *(const uint2*)&As[(row + 8) * GLD + ko];
                a[f][0] = lo.x; a[f][1] = hi.x; a[f][2] = lo.y; a[f][3] = hi.y;
            }
            #pragma unroll
            for (int nf = 0; nf < 8; nf++) {
                uint2 bb = *(const uint2*)&Bs[(wn + nf * 8 + r) * GLD + ko];
                mma8(acc[0][nf][0], acc[0][nf][1], acc[0][nf][2], acc[0][nf][3],
                     a[0][0], a[0][1], a[0][2], a[0][3], bb.x, bb.y);
                mma8(acc[1][nf][0], acc[1][nf][1], acc[1][nf][2], acc[1][nf][3],
                     a[1][0], a[1][1], a[1][2], a[1][3], bb.x, bb.y);
            }
        }
        if (kb + 2 < 28) {
            int ns = (kb + 2) % 3;
            gemm_issue(A, B, sg + ns * 2 * GSTG, sg + ns * 2 * GSTG + GSTG,
                       kb + 2, m0, n0, tid);
        } else {
            cp_commit();
        }
    }

    int posE = (lc < 2) ? 4 * lc : 4 * lc - 7;       // kperm(2lc)
    int posO = (lc < 2) ? 4 * lc + 2 : 4 * lc - 5;   // kperm(2lc+1)
    #pragma unroll
    for (int f = 0; f < 2; f++) {
        int row = m0 + wm + f * 16 + r;
        #pragma unroll
        for (int nf = 0; nf < 8; nf++) {
            int cb = n0 + wn + nf * 8;
            if (PERM) {
                C[(size_t)row * ldc + cb + posE] = f2tf(acc[f][nf][0]);
                C[(size_t)row * ldc + cb + posO] = f2tf(acc[f][nf][1]);
                C[(size_t)(row + 8) * ldc + cb + posE] = f2tf(acc[f][nf][2]);
                C[(size_t)(row + 8) * ldc + cb + posO] = f2tf(acc[f][nf][3]);
            } else {
                *(float2*)&C[(size_t)row * ldc + cb + 2 * lc] =
                    make_float2(acc[f][nf][0], acc[f][nf][1]);
                *(float2*)&C[(size_t)(row + 8) * ldc + cb + 2 * lc] =
                    make_float2(acc[f][nf][2], acc[f][nf][3]);
            }
        }
    }
}

__global__ void __launch_bounds__(256, 2) proj_tc()
{
    int z = blockIdx.y;
    float* out = ((z % 3) == 0 ? g_q : ((z % 3) == 1 ? g_k : g_v)) + (size_t)(z / 3) * MTOT * HD;
    gemm_main<true>(g_xt, g_wt + (size_t)z * HD * HID, out, HD, blockIdx.x * 128, 0);
}

__global__ void __launch_bounds__(256, 2) outproj_tc(float* __restrict__ out)
{
    gemm_main<false>(g_att, g_wot, out, HID, blockIdx.x * 128, blockIdx.y * 128);
}

// ===========================================================================
// Flash attention: compact phase pipelined with cp.async (K & V pure copies),
// trimmed band tiles, reversed mt order.  BM=64, BN=64, 128 threads.
// ===========================================================================
#define KB_LD 132
#define VB_LD 68
#define P_LD  68
#define KB_FL (64 * KB_LD)    // 8448
#define VB_FL (128 * VB_LD)   // 8704
#define PS_FL (64 * P_LD)     // 4352
#define ATTN_SM ((KB_FL + VB_FL + PS_FL) * 4)   // 86016 B

#define SCLC (0.08838834764831845f * 1.4426950408889634f)

// Band tile (non-compact): NFB = number of 8-col fragments (8, 4 or 2)
template<int NFB>
__device__ __forceinline__ void band_tile(
    int bstart, int causal,
    const float* __restrict__ Kf, const float* __restrict__ Vf,
    float* Kb, float* Vb, float* Ps,
    const unsigned (&qf)[16][4], float (&o)[16][4],
    float& m_lo, float& m_hi, float& l_lo, float& l_hi,
    int tid, int r, int lc, int rloc, int rowq, int posE, int posO)
{
    // stage K rows [bstart, bstart+8*NFB)
    #pragma unroll
    for (int j = 0; j < NFB * 2; j++) {
        int idx = tid + 128 * j;
        int nn = idx >> 5, ch = idx & 31;
        int og = bstart + nn;
        float4 v = (og >= 0 && og < TT)
            ? *(const float4*)(Kf + (size_t)og * HD + ch * 4)
            : make_float4(0.f, 0.f, 0.f, 0.f);
        *(float4*)&Kb[nn * KB_LD + ch * 4] = v;
    }
    __syncthreads();

    float s[NFB][4];
    #pragma unroll
    for (int nf = 0; nf < NFB; nf++)
        #pragma unroll
        for (int e = 0; e < 4; e++) s[nf][e] = 0.f;
    #pragma unroll
    for (int kb = 0; kb < 16; kb++) {
        #pragma unroll
        for (int nf = 0; nf < NFB; nf++) {
            uint2 bb = *(const uint2*)&Kb[(nf * 8 + r) * KB_LD + kb * 8 + 2 * lc];
            mma8(s[nf][0], s[nf][1], s[nf][2], s[nf][3],
                 qf[kb][0], qf[kb][1], qf[kb][2], qf[kb][3], bb.x, bb.y);
        }
    }

    float mx_lo = -1e30f, mx_hi = -1e30f;
    int gi_lo = rowq, gi_hi = rowq + 8;
    #pragma unroll
    for (int nf = 0; nf < NFB; nf++) {
        #pragma unroll
        for (int t = 0; t < 2; t++) {
            int og = bstart + nf * 8 + 2 * lc + t;
            bool ok_lo, ok_hi;
            if (causal) {
                ok_lo = (og >= gi_lo - 16) && (og <= gi_lo) && (og >= 0);
                ok_hi = (og >= gi_hi - 16) && (og <= gi_hi) && (og >= 0);
            } else {
                bool inr = (og >= 0) && (og < TT);
                ok_lo = inr && (og >= gi_lo - 16) && (og <= gi_lo + 16);
                ok_hi = inr && (og >= gi_hi - 16) && (og <= gi_hi + 16);
            }
            float vlo = ok_lo ? s[nf][t] * SCLC : -1e30f;
            float vhi = ok_hi ? s[nf][2 + t] * SCLC : -1e30f;
            s[nf][t] = vlo; s[nf][2 + t] = vhi;
            mx_lo = fmaxf(mx_lo, vlo); mx_hi = fmaxf(mx_hi, vhi);
        }
    }
    mx_lo = fmaxf(mx_lo, __shfl_xor_sync(0xffffffffu, mx_lo, 1));
    mx_lo = fmaxf(mx_lo, __shfl_xor_sync(0xffffffffu, mx_lo, 2));
    mx_hi = fmaxf(mx_hi, __shfl_xor_sync(0xffffffffu, mx_hi, 1));
    mx_hi = fmaxf(mx_hi, __shfl_xor_sync(0xffffffffu, mx_hi, 2));

    float mn_lo = fmaxf(fmaxf(m_lo, mx_lo), -1e28f);
    float mn_hi = fmaxf(fmaxf(m_hi, mx_hi), -1e28f);
    float cor_lo = exp2f(m_lo - mn_lo), cor_hi = exp2f(m_hi - mn_hi);
    m_lo = mn_lo; m_hi = mn_hi;

    float sum_lo = 0.f, sum_hi = 0.f;
    #pragma unroll
    for (int nf = 0; nf < NFB; nf++) {
        float p0 = exp2f(s[nf][0] - mn_lo);
        float p1 = exp2f(s[nf][1] - mn_lo);
        float p2 = exp2f(s[nf][2] - mn_hi);
        float p3 = exp2f(s[nf][3] - mn_hi);
        sum_lo += p0 + p1; sum_hi += p2 + p3;
        Ps[rloc * P_LD + nf * 8 + posE] = f2tf(p0);
        Ps[rloc * P_LD + nf * 8 + posO] = f2tf(p1);
        Ps[(rloc + 8) * P_LD + nf * 8 + posE] = f2tf(p2);
        Ps[(rloc + 8) * P_LD + nf * 8 + posO] = f2tf(p3);
    }
    sum_lo += __shfl_xor_sync(0xffffffffu, sum_lo, 1);
    sum_lo += __shfl_xor_sync(0xffffffffu, sum_lo, 2);
    sum_hi += __shfl_xor_sync(0xffffffffu, sum_hi, 1);
    sum_hi += __shfl_xor_sync(0xffffffffu, sum_hi, 2);
    l_lo = l_lo * cor_lo + sum_lo;
    l_hi = l_hi * cor_hi + sum_hi;
    #pragma unroll
    for (int nf = 0; nf < 16; nf++) {
        o[nf][0] *= cor_lo; o[nf][1] *= cor_lo;
        o[nf][2] *= cor_hi; o[nf][3] *= cor_hi;
    }
    __syncthreads();

    // stage V transposed into Vb (source g_v is d-permuted; unpermute via bse)
    #pragma unroll
    for (int j = 0; j < NFB * 2; j++) {
        int idx = tid + 128 * j;
        int ss = idx % (NFB * 8), dq = idx / (NFB * 8);
        int og = bstart + ss;
        float4 v = (og >= 0 && og < TT)
            ? *(const float4*)(Vf + (size_t)og * HD + dq * 4)
            : make_float4(0.f, 0.f, 0.f, 0.f);
        int ps = kperm(ss);
        int bse = (dq >> 1) * 8 + ((dq & 1) ? 2 : 0);
        Vb[(bse + 0) * VB_LD + ps] = v.x;
        Vb[(bse + 4) * VB_LD + ps] = v.y;
        Vb[(bse + 1) * VB_LD + ps] = v.z;
        Vb[(bse + 5) * VB_LD + ps] = v.w;
    }
    __syncthreads();

    #pragma unroll
    for (int kb = 0; kb < NFB; kb++) {
        uint2 plo = *(const uint2*)&Ps[rloc * P_LD + kb * 8 + 2 * lc];
        uint2 phi = *(const uint2*)&Ps[(rloc + 8) * P_LD + kb * 8 + 2 * lc];
        #pragma unroll
        for (int nf = 0; nf < 16; nf++) {
            uint2 bb = *(const uint2*)&Vb[(nf * 8 + r) * VB_LD + kb * 8 + 2 * lc];
            mma8(o[nf][0], o[nf][1], o[nf][2], o[nf][3],
                 plo.x, phi.x, plo.y, phi.y, bb.x, bb.y);
        }
    }
    __syncthreads();
}

__global__ void __launch_bounds__(128, 2) attn_tc(const int* __restrict__ causal_p)
{
    extern __shared__ float sm[];
    float* Kb = sm;
    float* Vb = sm + KB_FL;
    float* Ps = sm + KB_FL + VB_FL;

    int tid = threadIdx.x, lane = tid & 31, wid = tid >> 5;
    int h = blockIdx.z, b = blockIdx.y;
    int mt = (TT / 64 - 1) - blockIdx.x;        // reversed: big tiles first
    int m0 = mt * 64;
    size_t base = (size_t)(h * BB + b);
    const float* Q   = g_q + base * TT * HD;
    const float* Kf  = g_k + base * TT * HD;
    const float* Vf  = g_v + base * TT * HD;
    const float* Kc  = g_kc + base * CPAD * HD;
    const float* VcT = g_vct + base * HD * CPAD;
    int causal = *causal_p;

    int s0, s1, s2, cnt;
    fano_lines(h, s0, s1, s2, cnt);

    int r = lane >> 2, lc = lane & 3;
    int rowq = m0 + wid * 16 + r;
    int rloc = wid * 16 + r;
    int posE = (lc < 2) ? 4 * lc : 4 * lc - 7;
    int posO = (lc < 2) ? 4 * lc + 2 : 4 * lc - 5;

    int nt_c;
    if (causal) {
        int x = m0 + 47;
        int qq = x / 7, rr = x % 7;
        int bound = 3 * qq + (s0 < rr) + (s1 < rr) + (s2 < rr);
        nt_c = (bound + 63) >> 6;
    } else {
        nt_c = CPAD / 64;
    }

    // prologue: kick off K(0), V(0) before anything else
    #pragma unroll
    for (int j = 0; j < 16; j++) {
        int idx = tid + 128 * j;
        int nn = idx >> 5, ch = idx & 31;
        cp16(&Kb[nn * KB_LD + ch * 4], Kc + (size_t)nn * HD + ch * 4);
    }
    cp_commit();
    #pragma unroll
    for (int j = 0; j < 16; j++) {
        int idx = tid + 128 * j;
        int dd = idx >> 4, ch = idx & 15;
        cp16(&Vb[dd * VB_LD + ch * 4], VcT + (size_t)dd * CPAD + ch * 4);
    }
    cp_commit();

    // Q fragments (pre-rounded, permuted gmem -> adjacent pairs)
    unsigned qf[16][4];
    #pragma unroll
    for (int kb = 0; kb < 16; kb++) {
        float2 qlo = *(const float2*)(Q + (size_t)rowq * HD + kb * 8 + 2 * lc);
        float2 qhi = *(const float2*)(Q + (size_t)(rowq + 8) * HD + kb * 8 + 2 * lc);
        qf[kb][0] = __float_as_uint(qlo.x); qf[kb][1] = __float_as_uint(qhi.x);
        qf[kb][2] = __float_as_uint(qlo.y); qf[kb][3] = __float_as_uint(qhi.y);
    }

    float o[16][4];
    #pragma unroll
    for (int nf = 0; nf < 16; nf++)
        #pragma unroll
        for (int e = 0; e < 4; e++) o[nf][e] = 0.f;
    float m_lo = -1e30f, m_hi = -1e30f, l_lo = 0.f, l_hi = 0.f;

    // ---- compact phase (pipelined) ----
    for (int n = 0; n < nt_c; n++) {
        int n0 = n * 64;
        cp_wait<1>();           // K(n) arrived
        __syncthreads();

        float s[8][4];
        #pragma unroll
        for (int nf = 0; nf < 8; nf++)
            #pragma unroll
            for (int e = 0; e < 4; e++) s[nf][e] = 0.f;
        #pragma unroll
        for (int kb = 0; kb < 16; kb++) {
            #pragma unroll
            for (int nf = 0; nf < 8; nf++) {
                uint2 bb = *(const uint2*)&Kb[(nf * 8 + r) * KB_LD + kb * 8 + 2 * lc];
                mma8(s[nf][0], s[nf][1], s[nf][2], s[nf][3],
                     qf[kb][0], qf[kb][1], qf[kb][2], qf[kb][3], bb.x, bb.y);
            }
        }
        __syncthreads();        // K reads done

        // issue K(n+1)
        if (n + 1 < nt_c) {
            int n1 = (n + 1) * 64;
            #pragma unroll
            for (int j = 0; j < 16; j++) {
                int idx = tid + 128 * j;
                int nn = idx >> 5, ch = idx & 31;
                cp16(&Kb[nn * KB_LD + ch * 4], Kc + (size_t)(n1 + nn) * HD + ch * 4);
            }
        }
        cp_commit();

        // mask + online softmax
        float mx_lo = -1e30f, mx_hi = -1e30f;
        int gi_lo = rowq, gi_hi = rowq + 8;
        #pragma unroll
        for (int nf = 0; nf < 8; nf++) {
            #pragma unroll
            for (int t = 0; t < 2; t++) {
                int cj = n0 + nf * 8 + 2 * lc + t;
                int qq = cj / 3, uu = cj - 3 * qq;
                int sl = (uu == 0) ? s0 : ((uu == 1) ? s1 : s2);
                int og = 7 * qq + sl;
                bool ok_lo, ok_hi;
                if (causal) { ok_lo = og <= gi_lo - 17; ok_hi = og <= gi_hi - 17; }
                else {
                    bool inr = og < TT;
                    ok_lo = inr && (og <= gi_lo - 17 || og >= gi_lo + 17);
                    ok_hi = inr && (og <= gi_hi - 17 || og >= gi_hi + 17);
                }
                float vlo = ok_lo ? s[nf][t] * SCLC : -1e30f;
                float vhi = ok_hi ? s[nf][2 + t] * SCLC : -1e30f;
                s[nf][t] = vlo; s[nf][2 + t] = vhi;
                mx_lo = fmaxf(mx_lo, vlo); mx_hi = fmaxf(mx_hi, vhi);
            }
        }
        mx_lo = fmaxf(mx_lo, __shfl_xor_sync(0xffffffffu, mx_lo, 1));
        mx_lo = fmaxf(mx_lo, __shfl_xor_sync(0xffffffffu, mx_lo, 2));
        mx_hi = fmaxf(mx_hi, __shfl_xor_sync(0xffffffffu, mx_hi, 1));
        mx_hi = fmaxf(mx_hi, __shfl_xor_sync(0xffffffffu, mx_hi, 2));

        float mn_lo = fmaxf(fmaxf(m_lo, mx_lo), -1e28f);
        float mn_hi = fmaxf(fmaxf(m_hi, mx_hi), -1e28f);
        float cor_lo = exp2f(m_lo - mn_lo), cor_hi = exp2f(m_hi - mn_hi);
        m_lo = mn_lo; m_hi = mn_hi;

        float sum_lo = 0.f, sum_hi = 0.f;
        #pragma unroll
        for (int nf = 0; nf < 8; nf++) {
            float p0 = exp2f(s[nf][0] - mn_lo);
            float p1 = exp2f(s[nf][1] - mn_lo);
            float p2 = exp2f(s[nf][2] - mn_hi);
            float p3 = exp2f(s[nf][3] - mn_hi);
            sum_lo += p0 + p1; sum_hi += p2 + p3;
            Ps[rloc * P_LD + nf * 8 + posE] = f2tf(p0);
            Ps[rloc * P_LD + nf * 8 + posO] = f2tf(p1);
            Ps[(rloc + 8) * P_LD + nf * 8 + posE] = f2tf(p2);
            Ps[(rloc + 8) * P_LD + nf * 8 + posO] = f2tf(p3);
        }
        sum_lo += __shfl_xor_sync(0xffffffffu, sum_lo, 1);
        sum_lo += __shfl_xor_sync(0xffffffffu, sum_lo, 2);
        sum_hi += __shfl_xor_sync(0xffffffffu, sum_hi, 1);
        sum_hi += __shfl_xor_sync(0xffffffffu, sum_hi, 2);
        l_lo = l_lo * cor_lo + sum_lo;
        l_hi = l_hi * cor_hi + sum_hi;
        #pragma unroll
        for (int nf = 0; nf < 16; nf++) {
            o[nf][0] *= cor_lo; o[nf][1] *= cor_lo;
            o[nf][2] *= cor_hi; o[nf][3] *= cor_hi;
        }

        cp_wait<1>();           // V(n) arrived
        __syncthreads();        // V + Ps visible

        #pragma unroll
        for (int kb = 0; kb < 8; kb++) {
            uint2 plo = *(const uint2*)&Ps[rloc * P_LD + kb * 8 + 2 * lc];
            uint2 phi = *(const uint2*)&Ps[(rloc + 8) * P_LD + kb * 8 + 2 * lc];
            #pragma unroll
            for (int nf = 0; nf < 16; nf++) {
                uint2 bb = *(const uint2*)&Vb[(nf * 8 + r) * VB_LD + kb * 8 + 2 * lc];
                mma8(o[nf][0], o[nf][1], o[nf][2], o[nf][3],
                     plo.x, phi.x, plo.y, phi.y, bb.x, bb.y);
            }
        }
        __syncthreads();        // V + Ps reads done

        // issue V(n+1)
        if (n + 1 < nt_c) {
            int n1 = (n + 1) * 64;
            #pragma unroll
            for (int j = 0; j < 16; j++) {
                int idx = tid + 128 * j;
                int dd = idx >> 4, ch = idx & 15;
                cp16(&Vb[dd * VB_LD + ch * 4], VcT + (size_t)dd * CPAD + n1 + ch * 4);
            }
        }
        cp_commit();
    }

    // ---- band tiles ----
    band_tile<8>(m0 - 16, causal, Kf, Vf, Kb, Vb, Ps, qf, o,
                 m_lo, m_hi, l_lo, l_hi, tid, r, lc, rloc, rowq, posE, posO);
    if (causal)
        band_tile<2>(m0 + 48, 1, Kf, Vf, Kb, Vb, Ps, qf, o,
                     m_lo, m_hi, l_lo, l_hi, tid, r, lc, rloc, rowq, posE, posO);
    else
        band_tile<4>(m0 + 48, 0, Kf, Vf, Kb, Vb, Ps, qf, o,
                     m_lo, m_hi, l_lo, l_hi, tid, r, lc, rloc, rowq, posE, posO);

    // epilogue: normalize, round, permuted concatenated-head layout
    float inv_lo = 1.f / l_lo, inv_hi = 1.f / l_hi;
    float* OPl = g_att + ((size_t)b * TT + rowq) * HID + h * HD;
    float* OPh = g_att + ((size_t)b * TT + rowq + 8) * HID + h * HD;
    #pragma unroll
    for (int nf = 0; nf < 16; nf++) {
        int cb = nf * 8;
        OPl[cb + posE] = f2tf(o[nf][0] * inv_lo);
        OPl[cb + posO] = f2tf(o[nf][1] * inv_lo);
        OPh[cb + posE] = f2tf(o[nf][2] * inv_hi);
        OPh[cb + posO] = f2tf(o[nf][3] * inv_hi);
    }
}

// ---------------------------------------------------------------------------
extern "C" void kernel_launch(void* const* d_in, const int* in_sizes, int n_in,
                              void* d_out, int out_size)
{
    const float* x  = (const float*)d_in[0];
    const float* Wq = (const float*)d_in[1];
    const float* Wk = (const float*)d_in[2];
    const float* Wv = (const float*)d_in[3];
    const float* Wo = (const float*)d_in[4];
    const int* isc  = (const int*)d_in[5];
    float* out = (float*)d_out;

    cudaFuncSetAttribute(proj_tc, cudaFuncAttributeMaxDynamicSharedMemorySize, GSMEM);
    cudaFuncSetAttribute(outproj_tc, cudaFuncAttributeMaxDynamicSharedMemorySize, GSMEM);
    cudaFuncSetAttribute(attn_tc, cudaFuncAttributeMaxDynamicSharedMemorySize, ATTN_SM);

    float* d_xt; cudaGetSymbolAddress((void**)&d_xt, g_xt);
    float* d_wot; cudaGetSymbolAddress((void**)&d_wot, g_wot);

    prep_perm<<<(MTOT * HID / 8 + 255) / 256, 256>>>(x, d_xt, MTOT * HID / 8);
    prep_perm<<<(HID * HID / 8 + 255) / 256, 256>>>(Wo, d_wot, HID * HID / 8);
    prep_wt<<<dim3(HID / 32, HD / 32, 21), dim3(32, 8)>>>(Wq, Wk, Wv);

    proj_tc<<<dim3(MTOT / 128, 21), 256, GSMEM>>>();
    compact_k<<<dim3(CPAD / 64, NH * BB), 256>>>();
    compact_vT<<<dim3(CPAD / 32, HD / 32, NH * BB), dim3(32, 8)>>>();
    attn_tc<<<dim3(TT / 64, BB, NH), 128, ATTN_SM>>>(isc);
    outproj_tc<<<dim3(MTOT / 128, HID / 128), 256, GSMEM>>>(out);
}

// round 7
// speedup vs baseline: 4.1432x; 1.0037x over previous
#include <cuda_runtime.h>

#define NH    7
#define HD    128
#define BB    4
#define TT    2048
#define HID   896
#define MTOT  (BB*TT)   // 8192
#define CPAD  896       // padded compact length (>= max 879, multiple of 64)

// Scratch (allocation-free rule: __device__ globals)
__device__ float g_xt[(size_t)MTOT * HID];            // x, tf32-rounded, 16-permuted
__device__ float g_wt[(size_t)21 * HD * HID];         // Wq/k/v transposed+rounded+perm
__device__ float g_wot[(size_t)HID * HID];            // Wo rounded+perm
__device__ float g_q[(size_t)NH * MTOT * HD];         // rounded, d 16-permuted
__device__ float g_k[(size_t)NH * MTOT * HD];
__device__ float g_v[(size_t)NH * MTOT * HD];
__device__ float g_kc[(size_t)NH * BB * CPAD * HD];   // Fano-compacted K [slot][d]
__device__ float g_vct[(size_t)NH * BB * HD * CPAD];  // compacted V^T [d][pos16(slot)]
__device__ float g_att[(size_t)MTOT * HID];           // rounded, permuted

// 16-perm: stored quad dq of each 16-group holds elements {dq, dq+4, dq+8, dq+12}.
// pos16(e) = 4*(e&3) + ((e&7)>>2) + 2*((e>>3)&1)  (within group)
// inv16(p) = 8*((p>>1)&1) + 4*(p&1) + (p>>2)

__device__ __forceinline__ float f2tf(float x) {
    unsigned u;
    asm("cvt.rna.tf32.f32 %0, %1;" : "=r"(u) : "f"(x));
    return __uint_as_float(u);
}

__device__ __forceinline__ void mma8(float& d0, float& d1, float& d2, float& d3,
                                     unsigned a0, unsigned a1, unsigned a2, unsigned a3,
                                     unsigned b0, unsigned b1) {
    asm volatile(
        "mma.sync.aligned.m16n8k8.row.col.f32.tf32.tf32.f32 "
        "{%0,%1,%2,%3}, {%4,%5,%6,%7}, {%8,%9}, {%0,%1,%2,%3};\n"
        : "+f"(d0), "+f"(d1), "+f"(d2), "+f"(d3)
        : "r"(a0), "r"(a1), "r"(a2), "r"(a3), "r"(b0), "r"(b1));
}

// 16B-chunk swizzle: logical chunk lch in row -> physical chunk
__device__ __forceinline__ int swch(int lch, int row) {
    return (lch & ~7) | ((lch & 7) ^ (row & 7));
}
// scalar address into a 64-float-wide swizzled tile
__device__ __forceinline__ int swps(int row, int p) {
    int chunk = p >> 2;
    return row * 64 + (((chunk & ~7) | ((chunk & 7) ^ (row & 7))) << 2) + (p & 3);
}

__device__ __forceinline__ void cp16(void* dst, const void* src) {
    unsigned d = (unsigned)__cvta_generic_to_shared(dst);
    asm volatile("cp.async.cg.shared.global [%0], [%1], 16;" :: "r"(d), "l"(src));
}
__device__ __forceinline__ void cp_commit() { asm volatile("cp.async.commit_group;"); }
template<int N> __device__ __forceinline__ void cp_wait() {
    asm volatile("cp.async.wait_group %0;" :: "n"(N));
}

// ===========================================================================
// Prep kernels: round to tf32 + 16-perm (a 4x4 transpose per 16-group)
// ===========================================================================
__global__ void prep_perm(const float* __restrict__ src, float* __restrict__ dst, int total16)
{
    int t = blockIdx.x * 256 + threadIdx.x;
    if (t >= total16) return;
    const float4* s = (const float4*)(src + (size_t)t * 16);
    float4 i0 = s[0], i1 = s[1], i2 = s[2], i3 = s[3];
    float4* d = (float4*)(dst + (size_t)t * 16);
    d[0] = make_float4(f2tf(i0.x), f2tf(i1.x), f2tf(i2.x), f2tf(i3.x));
    d[1] = make_float4(f2tf(i0.y), f2tf(i1.y), f2tf(i2.y), f2tf(i3.y));
    d[2] = make_float4(f2tf(i0.z), f2tf(i1.z), f2tf(i2.z), f2tf(i3.z));
    d[3] = make_float4(f2tf(i0.w), f2tf(i1.w), f2tf(i2.w), f2tf(i3.w));
}

// W[h][896][128] -> g_wt[z][n][896] (transposed, rounded, k 16-permuted)
__global__ void prep_wt(const float* __restrict__ Wq, const float* __restrict__ Wk,
                        const float* __restrict__ Wv)
{
    __shared__ float tb[32][33];
    int z = blockIdx.z, h = z / 3, sel = z % 3;
    const float* W = (sel == 0 ? Wq : (sel == 1 ? Wk : Wv)) + (size_t)h * HID * HD;
    int k0 = blockIdx.x * 32, n0 = blockIdx.y * 32;
    int tx = threadIdx.x, ty = threadIdx.y;
    #pragma unroll
    for (int i = 0; i < 4; i++)
        tb[ty + 8 * i][tx] = W[(size_t)(k0 + ty + 8 * i) * HD + n0 + tx];
    __syncthreads();
    // stored pos tx holds element al (inv16)
    int al = (tx & ~15) + 8 * ((tx >> 1) & 1) + 4 * (tx & 1) + ((tx & 15) >> 2);
    #pragma unroll
    for (int i = 0; i < 4; i++) {
        int n = n0 + ty + 8 * i;
        g_wt[((size_t)z * HD + n) * HID + k0 + tx] = f2tf(tb[al][ty + 8 * i]);
    }
}

__device__ __forceinline__ void fano_lines(int h, int& s0, int& s1, int& s2, int& cnt)
{
    int t;
    s0 = h; s1 = (h + 1) % 7; s2 = (h + 3) % 7;
    if (s0 > s1) { t = s0; s0 = s1; s1 = t; }
    if (s1 > s2) { t = s1; s1 = s2; s2 = t; }
    if (s0 > s1) { t = s0; s0 = s1; s1 = t; }
    cnt = 3 * 292 + (s0 < 4) + (s1 < 4) + (s2 < 4);
}

// K compaction: gather line columns into dense [slot][d] (d-perm carried along)
__global__ void __launch_bounds__(256) compact_k()
{
    int h = blockIdx.y >> 2, b = blockIdx.y & 3;
    int tid = threadIdx.x;
    int c = blockIdx.x * 64 + (tid >> 2);
    int seg = tid & 3;
    int s0, s1, s2, cnt;
    fano_lines(h, s0, s1, s2, cnt);
    int q = c / 3, u = c - 3 * q;
    int sl = (u == 0) ? s0 : ((u == 1) ? s1 : s2);
    int o = 7 * q + sl;
    bool valid = c < cnt;
    size_t sb = ((size_t)(h * BB + b) * TT + o) * HD + seg * 32;
    size_t db = ((size_t)(h * BB + b) * CPAD + c) * HD + seg * 32;
    float4 z4 = make_float4(0.f, 0.f, 0.f, 0.f);
    #pragma unroll
    for (int i = 0; i < 8; i++)
        *(float4*)&g_kc[db + i * 4] = valid ? *(const float4*)&g_k[sb + i * 4] : z4;
}

// V compaction + transpose: g_vct[d_actual][pos16(slot)] = V[slot][d_actual]
__global__ void compact_vT()   // grid (CPAD/32, HD/32, 28), block (32, 8)
{
    __shared__ float tb[32][33];
    int z = blockIdx.z, h = z >> 2, b = z & 3;
    int s0, s1, s2, cnt;
    fano_lines(h, s0, s1, s2, cnt);
    int c0 = blockIdx.x * 32, d0 = blockIdx.y * 32;
    int tx = threadIdx.x, ty = threadIdx.y;
    size_t srcb = (size_t)(h * BB + b) * TT * HD;
    size_t dstb = (size_t)(h * BB + b) * HD * CPAD;
    // source stored pos tx holds actual element al
    int al = (tx & ~15) + 8 * ((tx >> 1) & 1) + 4 * (tx & 1) + ((tx & 15) >> 2);
    #pragma unroll
    for (int i = 0; i < 4; i++) {
        int c = c0 + ty + 8 * i;
        int q = c / 3, u = c - 3 * q;
        int sl = (u == 0) ? s0 : ((u == 1) ? s1 : s2);
        int og = 7 * q + sl;
        float val = (c < cnt) ? g_v[srcb + (size_t)og * HD + d0 + tx] : 0.f;
        tb[ty + 8 * i][al] = val;           // [c_local][actual d_local]
    }
    __syncthreads();
    // dest slot position = pos16(c)
    int destc = c0 + (tx & ~15) + 4 * (tx & 3) + ((tx & 7) >> 2) + 2 * ((tx >> 3) & 1);
    #pragma unroll
    for (int i = 0; i < 4; i++) {
        int d = d0 + ty + 8 * i;
        g_vct[dstb + (size_t)d * CPAD + destc] = tb[tx][ty + 8 * i];
    }
}

// ===========================================================================
// tf32 GEMM: 128x128 CTA tile, 4 warps (64x64 each), BK=32, 3-stage cp.async,
// XOR-swizzled 32-float rows, LDS.128 fragments covering 2 k-steps.
// ===========================================================================
#define GSTG 4096                        // floats per (A or B) stage (128*32)
#define GSMEM (3 * 2 * GSTG * 4)         // 98304 B

__device__ __forceinline__ void gemm_issue(const float* __restrict__ A,
                                           const float* __restrict__ B,
                                           float* As, float* Bs,
                                           int kb, int m0, int n0, int tid)
{
    #pragma unroll
    for (int j = 0; j < 8; j++) {
        int idx = tid + 128 * j;
        int row = idx >> 3, ch = idx & 7;
        cp16(As + row * 32 + swch(ch, row) * 4, A + (size_t)(m0 + row) * HID + kb * 32 + ch * 4);
    }
    #pragma unroll
    for (int j = 0; j < 8; j++) {
        int idx = tid + 128 * j;
        int row = idx >> 3, ch = idx & 7;
        cp16(Bs + row * 32 + swch(ch, row) * 4, B + (size_t)(n0 + row) * HID + kb * 32 + ch * 4);
    }
    cp_commit();
}

template<bool PERM>
__device__ __forceinline__ void gemm_main(const float* __restrict__ A,
                                          const float* __restrict__ B,
                                          float* __restrict__ C, int ldc,
                                          int m0, int n0)
{
    extern __shared__ float sg[];
    int tid = threadIdx.x, lane = tid & 31, wid = tid >> 5;
    int wm = (wid >> 1) * 64, wn = (wid & 1) * 64;
    int r = lane >> 2, lc = lane & 3;

    float acc[4][8][4];
    #pragma unroll
    for (int f = 0; f < 4; f++)
        #pragma unroll
        for (int nf = 0; nf < 8; nf++)
            #pragma unroll
            for (int e = 0; e < 4; e++) acc[f][nf][e] = 0.f;

    gemm_issue(A, B, sg, sg + GSTG, 0, m0, n0, tid);
    gemm_issue(A, B, sg + 2 * GSTG, sg + 3 * GSTG, 1, m0, n0, tid);

    #pragma unroll 1
    for (int kb = 0; kb < 28; kb++) {
        int st = kb % 3;
        float* As = sg + st * 2 * GSTG;
        float* Bs = As + GSTG;
        cp_wait<1>();
        __syncthreads();
        #pragma unroll
        for (int g = 0; g < 2; g++) {
            int off = swch(g * 4 + lc, r) * 4;
            uint4 alo[4], ahi[4], bb[8];
            #pragma unroll
            for (int mf = 0; mf < 4; mf++) {
                int row = wm + mf * 16 + r;
                alo[mf] = *(const uint4*)&As[row * 32 + off];
                ahi[mf] = *(const uint4*)&As[(row + 8) * 32 + off];
            }
            #pragma unroll
            for (int nf = 0; nf < 8; nf++)
                bb[nf] = *(const uint4*)&Bs[(wn + nf * 8 + r) * 32 + off];
            #pragma unroll
            for (int mf = 0; mf < 4; mf++)
                #pragma unroll
                for (int nf = 0; nf < 8; nf++)
                    mma8(acc[mf][nf][0], acc[mf][nf][1], acc[mf][nf][2], acc[mf][nf][3],
                         alo[mf].x, ahi[mf].x, alo[mf].y, ahi[mf].y, bb[nf].x, bb[nf].y);
            #pragma unroll
            for (int mf = 0; mf < 4; mf++)
                #pragma unroll
                for (int nf = 0; nf < 8; nf++)
                    mma8(acc[mf][nf][0], acc[mf][nf][1], acc[mf][nf][2], acc[mf][nf][3],
                         alo[mf].z, ahi[mf].z, alo[mf].w, ahi[mf].w, bb[nf].z, bb[nf].w);
        }
        if (kb + 2 < 28) {
            int ns = (kb + 2) % 3;
            gemm_issue(A, B, sg + ns * 2 * GSTG, sg + ns * 2 * GSTG + GSTG,
                       kb + 2, m0, n0, tid);
        } else {
            cp_commit();
        }
    }

    int pbase = (lc & 1) * 8 + (lc >> 1);
    #pragma unroll
    for (int mf = 0; mf < 4; mf++) {
        int row = m0 + wm + mf * 16 + r;
        #pragma unroll
        for (int nf = 0; nf < 8; nf++) {
            if (PERM) {
                int cb = n0 + wn + (nf >> 1) * 16 + 2 * (nf & 1) + pbase;
                C[(size_t)row * ldc + cb]     = f2tf(acc[mf][nf][0]);
                C[(size_t)row * ldc + cb + 4] = f2tf(acc[mf][nf][1]);
                C[(size_t)(row + 8) * ldc + cb]     = f2tf(acc[mf][nf][2]);
                C[(size_t)(row + 8) * ldc + cb + 4] = f2tf(acc[mf][nf][3]);
            } else {
                int cb = n0 + wn + nf * 8 + 2 * lc;
                *(float2*)&C[(size_t)row * ldc + cb] =
                    make_float2(acc[mf][nf][0], acc[mf][nf][1]);
                *(float2*)&C[(size_t)(row + 8) * ldc + cb] =
                    make_float2(acc[mf][nf][2], acc[mf][nf][3]);
            }
        }
    }
}

__global__ void __launch_bounds__(128, 2) proj_tc()
{
    int z = blockIdx.y;
    float* out = ((z % 3) == 0 ? g_q : ((z % 3) == 1 ? g_k : g_v)) + (size_t)(z / 3) * MTOT * HD;
    gemm_main<true>(g_xt, g_wt + (size_t)z * HD * HID, out, HD, blockIdx.x * 128, 0);
}

__global__ void __launch_bounds__(128, 2) outproj_tc(float* __restrict__ out)
{
    gemm_main<false>(g_att, g_wot, out, HID, blockIdx.x * 128, blockIdx.y * 128);
}

// ===========================================================================
// Flash attention: pipelined compact phase, trimmed band, XOR-swizzled smem,
// LDS.128 double-k-step fragments.  BM=64, BN=64, 128 threads.
// ===========================================================================
#define KB_FL (64 * 128)      // 8192
#define VB_FL (128 * 64)      // 8192
#define PS_FL (64 * 64)       // 4096
#define ATTN_SM ((KB_FL + VB_FL + PS_FL) * 4)   // 81920 B

#define SCLC (0.08838834764831845f * 1.4426950408889634f)

template<int NFB>
__device__ __forceinline__ void band_tile(
    int bstart, int causal,
    const float* __restrict__ Kf, const float* __restrict__ Vf,
    float* Kb, float* Vb, float* Ps,
    const unsigned (&qf)[16][4], float (&o)[16][4],
    float& m_lo, float& m_hi, float& l_lo, float& l_hi,
    int tid, int r, int lc, int rloc, int rowq, int pbase)
{
    // stage K rows [bstart, bstart+8*NFB) with swizzle
    #pragma unroll
    for (int j = 0; j < NFB * 2; j++) {
        int idx = tid + 128 * j;
        int nn = idx >> 5, ch = idx & 31;
        int og = bstart + nn;
        float4 v = (og >= 0 && og < TT)
            ? *(const float4*)(Kf + (size_t)og * HD + ch * 4)
            : make_float4(0.f, 0.f, 0.f, 0.f);
        *(float4*)&Kb[nn * 128 + swch(ch, nn) * 4] = v;
    }
    __syncthreads();

    float s[NFB][4];
    #pragma unroll
    for (int nf = 0; nf < NFB; nf++)
        #pragma unroll
        for (int e = 0; e < 4; e++) s[nf][e] = 0.f;
    #pragma unroll
    for (int kb16 = 0; kb16 < 8; kb16++) {
        int off = swch(kb16 * 4 + lc, r) * 4;
        #pragma unroll
        for (int nf = 0; nf < NFB; nf++) {
            uint4 bb = *(const uint4*)&Kb[(nf * 8 + r) * 128 + off];
            mma8(s[nf][0], s[nf][1], s[nf][2], s[nf][3],
                 qf[2 * kb16][0], qf[2 * kb16][1], qf[2 * kb16][2], qf[2 * kb16][3],
                 bb.x, bb.y);
            mma8(s[nf][0], s[nf][1], s[nf][2], s[nf][3],
                 qf[2 * kb16 + 1][0], qf[2 * kb16 + 1][1], qf[2 * kb16 + 1][2], qf[2 * kb16 + 1][3],
                 bb.z, bb.w);
        }
    }

    float mx_lo = -1e30f, mx_hi = -1e30f;
    int gi_lo = rowq, gi_hi = rowq + 8;
    #pragma unroll
    for (int nf = 0; nf < NFB; nf++) {
        #pragma unroll
        for (int t = 0; t < 2; t++) {
            int og = bstart + nf * 8 + 2 * lc + t;
            bool ok_lo, ok_hi;
            if (causal) {
                ok_lo = (og >= gi_lo - 16) && (og <= gi_lo) && (og >= 0);
                ok_hi = (og >= gi_hi - 16) && (og <= gi_hi) && (og >= 0);
            } else {
                bool inr = (og >= 0) && (og < TT);
                ok_lo = inr && (og >= gi_lo - 16) && (og <= gi_lo + 16);
                ok_hi = inr && (og >= gi_hi - 16) && (og <= gi_hi + 16);
            }
            float vlo = ok_lo ? s[nf][t] * SCLC : -1e30f;
            float vhi = ok_hi ? s[nf][2 + t] * SCLC : -1e30f;
            s[nf][t] = vlo; s[nf][2 + t] = vhi;
            mx_lo = fmaxf(mx_lo, vlo); mx_hi = fmaxf(mx_hi, vhi);
        }
    }
    mx_lo = fmaxf(mx_lo, __shfl_xor_sync(0xffffffffu, mx_lo, 1));
    mx_lo = fmaxf(mx_lo, __shfl_xor_sync(0xffffffffu, mx_lo, 2));
    mx_hi = fmaxf(mx_hi, __shfl_xor_sync(0xffffffffu, mx_hi, 1));
    mx_hi = fmaxf(mx_hi, __shfl_xor_sync(0xffffffffu, mx_hi, 2));

    float mn_lo = fmaxf(fmaxf(m_lo, mx_lo), -1e28f);
    float mn_hi = fmaxf(fmaxf(m_hi, mx_hi), -1e28f);
    float cor_lo = exp2f(m_lo - mn_lo), cor_hi = exp2f(m_hi - mn_hi);
    m_lo = mn_lo; m_hi = mn_hi;

    float sum_lo = 0.f, sum_hi = 0.f;
    #pragma unroll
    for (int nf = 0; nf < NFB; nf++) {
        float p0 = exp2f(s[nf][0] - mn_lo);
        float p1 = exp2f(s[nf][1] - mn_lo);
        float p2 = exp2f(s[nf][2] - mn_hi);
        float p3 = exp2f(s[nf][3] - mn_hi);
        sum_lo += p0 + p1; sum_hi += p2 + p3;
        int pe = (nf >> 1) * 16 + 2 * (nf & 1) + pbase;
        Ps[swps(rloc, pe)]         = f2tf(p0);
        Ps[swps(rloc, pe + 4)]     = f2tf(p1);
        Ps[swps(rloc + 8, pe)]     = f2tf(p2);
        Ps[swps(rloc + 8, pe + 4)] = f2tf(p3);
    }
    sum_lo += __shfl_xor_sync(0xffffffffu, sum_lo, 1);
    sum_lo += __shfl_xor_sync(0xffffffffu, sum_lo, 2);
    sum_hi += __shfl_xor_sync(0xffffffffu, sum_hi, 1);
    sum_hi += __shfl_xor_sync(0xffffffffu, sum_hi, 2);
    l_lo = l_lo * cor_lo + sum_lo;
    l_hi = l_hi * cor_hi + sum_hi;
    #pragma unroll
    for (int nf = 0; nf < 16; nf++) {
        o[nf][0] *= cor_lo; o[nf][1] *= cor_lo;
        o[nf][2] *= cor_hi; o[nf][3] *= cor_hi;
    }
    __syncthreads();

    // stage V transposed into Vb; g_v d-quads hold actual d {c, c+4, c+8, c+12}
    #pragma unroll
    for (int j = 0; j < NFB * 2; j++) {
        int idx = tid + 128 * j;
        int ss = idx % (NFB * 8), dq = idx / (NFB * 8);
        int og = bstart + ss;
        float4 v = (og >= 0 && og < TT)
            ? *(const float4*)(Vf + (size_t)og * HD + dq * 4)
            : make_float4(0.f, 0.f, 0.f, 0.f);
        int ps = (ss & ~15) + 4 * (ss & 3) + ((ss & 7) >> 2) + 2 * ((ss >> 3) & 1);
        int d0 = (dq >> 2) * 16 + (dq & 3);
        Vb[swps(d0, ps)]      = v.x;
        Vb[swps(d0 + 4, ps)]  = v.y;
        Vb[swps(d0 + 8, ps)]  = v.z;
        Vb[swps(d0 + 12, ps)] = v.w;
    }
    __syncthreads();

    #pragma unroll
    for (int g = 0; g < NFB / 2; g++) {
        int off = swch(g * 4 + lc, r) * 4;
        uint4 plo = *(const uint4*)&Ps[rloc * 64 + off];
        uint4 phi = *(const uint4*)&Ps[(rloc + 8) * 64 + off];
        #pragma unroll
        for (int nf = 0; nf < 16; nf++) {
            uint4 vv = *(const uint4*)&Vb[(nf * 8 + r) * 64 + off];
            mma8(o[nf][0], o[nf][1], o[nf][2], o[nf][3],
                 plo.x, phi.x, plo.y, phi.y, vv.x, vv.y);
            mma8(o[nf][0], o[nf][1], o[nf][2], o[nf][3],
                 plo.z, phi.z, plo.w, phi.w, vv.z, vv.w);
        }
    }
    __syncthreads();
}

__global__ void __launch_bounds__(128, 2) attn_tc(const int* __restrict__ causal_p)
{
    extern __shared__ float sm[];
    float* Kb = sm;
    float* Vb = sm + KB_FL;
    float* Ps = sm + KB_FL + VB_FL;

    int tid = threadIdx.x, lane = tid & 31, wid = tid >> 5;
    int h = blockIdx.z, b = blockIdx.y;
    int mt = (TT / 64 - 1) - blockIdx.x;        // reversed: big tiles first
    int m0 = mt * 64;
    size_t base = (size_t)(h * BB + b);
    const float* Q   = g_q + base * TT * HD;
    const float* Kf  = g_k + base * TT * HD;
    const float* Vf  = g_v + base * TT * HD;
    const float* Kc  = g_kc + base * CPAD * HD;
    const float* VcT = g_vct + base * HD * CPAD;
    int causal = *causal_p;

    int s0, s1, s2, cnt;
    fano_lines(h, s0, s1, s2, cnt);

    int r = lane >> 2, lc = lane & 3;
    int rowq = m0 + wid * 16 + r;
    int rloc = wid * 16 + r;
    int pbase = (lc & 1) * 8 + (lc >> 1);

    int nt_c;
    if (causal) {
        int x = m0 + 47;
        int qq = x / 7, rr = x % 7;
        int bound = 3 * qq + (s0 < rr) + (s1 < rr) + (s2 < rr);
        nt_c = (bound + 63) >> 6;
    } else {
        nt_c = CPAD / 64;
    }

    // prologue: kick off K(0), V(0)
    #pragma unroll
    for (int j = 0; j < 16; j++) {
        int idx = tid + 128 * j;
        int nn = idx >> 5, ch = idx & 31;
        cp16(&Kb[nn * 128 + swch(ch, nn) * 4], Kc + (size_t)nn * HD + ch * 4);
    }
    cp_commit();
    #pragma unroll
    for (int j = 0; j < 16; j++) {
        int idx = tid + 128 * j;
        int dd = idx >> 4, ch = idx & 15;
        cp16(&Vb[dd * 64 + swch(ch, dd) * 4], VcT + (size_t)dd * CPAD + ch * 4);
    }
    cp_commit();

    // Q fragments: uint4 covers 2 k-steps
    unsigned qf[16][4];
    #pragma unroll
    for (int kb16 = 0; kb16 < 8; kb16++) {
        uint4 rlo = *(const uint4*)(Q + (size_t)rowq * HD + kb16 * 16 + 4 * lc);
        uint4 rhi = *(const uint4*)(Q + (size_t)(rowq + 8) * HD + kb16 * 16 + 4 * lc);
        qf[2 * kb16][0] = rlo.x; qf[2 * kb16][1] = rhi.x;
        qf[2 * kb16][2] = rlo.y; qf[2 * kb16][3] = rhi.y;
        qf[2 * kb16 + 1][0] = rlo.z; qf[2 * kb16 + 1][1] = rhi.z;
        qf[2 * kb16 + 1][2] = rlo.w; qf[2 * kb16 + 1][3] = rhi.w;
    }

    float o[16][4];
    #pragma unroll
    for (int nf = 0; nf < 16; nf++)
        #pragma unroll
        for (int e = 0; e < 4; e++) o[nf][e] = 0.f;
    float m_lo = -1e30f, m_hi = -1e30f, l_lo = 0.f, l_hi = 0.f;

    // ---- compact phase (pipelined) ----
    for (int n = 0; n < nt_c; n++) {
        int n0 = n * 64;
        cp_wait<1>();           // K(n) arrived
        __syncthreads();

        float s[8][4];
        #pragma unroll
        for (int nf = 0; nf < 8; nf++)
            #pragma unroll
            for (int e = 0; e < 4; e++) s[nf][e] = 0.f;
        #pragma unroll
        for (int kb16 = 0; kb16 < 8; kb16++) {
            int off = swch(kb16 * 4 + lc, r) * 4;
            #pragma unroll
            for (int nf = 0; nf < 8; nf++) {
                uint4 bb = *(const uint4*)&Kb[(nf * 8 + r) * 128 + off];
                mma8(s[nf][0], s[nf][1], s[nf][2], s[nf][3],
                     qf[2 * kb16][0], qf[2 * kb16][1], qf[2 * kb16][2], qf[2 * kb16][3],
                     bb.x, bb.y);
                mma8(s[nf][0], s[nf][1], s[nf][2], s[nf][3],
                     qf[2 * kb16 + 1][0], qf[2 * kb16 + 1][1], qf[2 * kb16 + 1][2], qf[2 * kb16 + 1][3],
                     bb.z, bb.w);
            }
        }
        __syncthreads();        // K reads done

        if (n + 1 < nt_c) {
            int n1 = (n + 1) * 64;
            #pragma unroll
            for (int j = 0; j < 16; j++) {
                int idx = tid + 128 * j;
                int nn = idx >> 5, ch = idx & 31;
                cp16(&Kb[nn * 128 + swch(ch, nn) * 4], Kc + (size_t)(n1 + nn) * HD + ch * 4);
            }
        }
        cp_commit();

        // mask + online softmax
        float mx_lo = -1e30f, mx_hi = -1e30f;
        int gi_lo = rowq, gi_hi = rowq + 8;
        #pragma unroll
        for (int nf = 0; nf < 8; nf++) {
            #pragma unroll
            for (int t = 0; t < 2; t++) {
                int cj = n0 + nf * 8 + 2 * lc + t;
                int qq = cj / 3, uu = cj - 3 * qq;
                int sl = (uu == 0) ? s0 : ((uu == 1) ? s1 : s2);
                int og = 7 * qq + sl;
                bool ok_lo, ok_hi;
                if (causal) { ok_lo = og <= gi_lo - 17; ok_hi = og <= gi_hi - 17; }
                else {
                    bool inr = og < TT;
                    ok_lo = inr && (og <= gi_lo - 17 || og >= gi_lo + 17);
                    ok_hi = inr && (og <= gi_hi - 17 || og >= gi_hi + 17);
                }
                float vlo = ok_lo ? s[nf][t] * SCLC : -1e30f;
                float vhi = ok_hi ? s[nf][2 + t] * SCLC : -1e30f;
                s[nf][t] = vlo; s[nf][2 + t] = vhi;
                mx_lo = fmaxf(mx_lo, vlo); mx_hi = fmaxf(mx_hi, vhi);
            }
        }
        mx_lo = fmaxf(mx_lo, __shfl_xor_sync(0xffffffffu, mx_lo, 1));
        mx_lo = fmaxf(mx_lo, __shfl_xor_sync(0xffffffffu, mx_lo, 2));
        mx_hi = fmaxf(mx_hi, __shfl_xor_sync(0xffffffffu, mx_hi, 1));
        mx_hi = fmaxf(mx_hi, __shfl_xor_sync(0xffffffffu, mx_hi, 2));

        float mn_lo = fmaxf(fmaxf(m_lo, mx_lo), -1e28f);
        float mn_hi = fmaxf(fmaxf(m_hi, mx_hi), -1e28f);
        float cor_lo = exp2f(m_lo - mn_lo), cor_hi = exp2f(m_hi - mn_hi);
        m_lo = mn_lo; m_hi = mn_hi;

        float sum_lo = 0.f, sum_hi = 0.f;
        #pragma unroll
        for (int nf = 0; nf < 8; nf++) {
            float p0 = exp2f(s[nf][0] - mn_lo);
            float p1 = exp2f(s[nf][1] - mn_lo);
            float p2 = exp2f(s[nf][2] - mn_hi);
            float p3 = exp2f(s[nf][3] - mn_hi);
            sum_lo += p0 + p1; sum_hi += p2 + p3;
            int pe = (nf >> 1) * 16 + 2 * (nf & 1) + pbase;
            Ps[swps(rloc, pe)]         = f2tf(p0);
            Ps[swps(rloc, pe + 4)]     = f2tf(p1);
            Ps[swps(rloc + 8, pe)]     = f2tf(p2);
            Ps[swps(rloc + 8, pe + 4)] = f2tf(p3);
        }
        sum_lo += __shfl_xor_sync(0xffffffffu, sum_lo, 1);
        sum_lo += __shfl_xor_sync(0xffffffffu, sum_lo, 2);
        sum_hi += __shfl_xor_sync(0xffffffffu, sum_hi, 1);
        sum_hi += __shfl_xor_sync(0xffffffffu, sum_hi, 2);
        l_lo = l_lo * cor_lo + sum_lo;
        l_hi = l_hi * cor_hi + sum_hi;
        #pragma unroll
        for (int nf = 0; nf < 16; nf++) {
            o[nf][0] *= cor_lo; o[nf][1] *= cor_lo;
            o[nf][2] *= cor_hi; o[nf][3] *= cor_hi;
        }

        cp_wait<1>();           // V(n) arrived
        __syncthreads();        // V + Ps visible

        #pragma unroll
        for (int g = 0; g < 4; g++) {
            int off = swch(g * 4 + lc, r) * 4;
            uint4 plo = *(const uint4*)&Ps[rloc * 64 + off];
            uint4 phi = *(const uint4*)&Ps[(rloc + 8) * 64 + off];
            #pragma unroll
            for (int nf = 0; nf < 16; nf++) {
                uint4 vv = *(const uint4*)&Vb[(nf * 8 + r) * 64 + off];
                mma8(o[nf][0], o[nf][1], o[nf][2], o[nf][3],
                     plo.x, phi.x, plo.y, phi.y, vv.x, vv.y);
                mma8(o[nf][0], o[nf][1], o[nf][2], o[nf][3],
                     plo.z, phi.z, plo.w, phi.w, vv.z, vv.w);
            }
        }
        __syncthreads();        // V + Ps reads done

        if (n + 1 < nt_c) {
            int n1 = (n + 1) * 64;
            #pragma unroll
            for (int j = 0; j < 16; j++) {
                int idx = tid + 128 * j;
                int dd = idx >> 4, ch = idx & 15;
                cp16(&Vb[dd * 64 + swch(ch, dd) * 4], VcT + (size_t)dd * CPAD + n1 + ch * 4);
            }
        }
        cp_commit();
    }

    // ---- band tiles ----
    band_tile<8>(m0 - 16, causal, Kf, Vf, Kb, Vb, Ps, qf, o,
                 m_lo, m_hi, l_lo, l_hi, tid, r, lc, rloc, rowq, pbase);
    if (causal)
        band_tile<2>(m0 + 48, 1, Kf, Vf, Kb, Vb, Ps, qf, o,
                     m_lo, m_hi, l_lo, l_hi, tid, r, lc, rloc, rowq, pbase);
    else
        band_tile<4>(m0 + 48, 0, Kf, Vf, Kb, Vb, Ps, qf, o,
                     m_lo, m_hi, l_lo, l_hi, tid, r, lc, rloc, rowq, pbase);

    // epilogue: normalize, round, permuted concatenated-head layout
    float inv_lo = 1.f / l_lo, inv_hi = 1.f / l_hi;
    float* OPl = g_att + ((size_t)b * TT + rowq) * HID + h * HD;
    float* OPh = g_att + ((size_t)b * TT + rowq + 8) * HID + h * HD;
    #pragma unroll
    for (int nf = 0; nf < 16; nf++) {
        int pe = (nf >> 1) * 16 + 2 * (nf & 1) + pbase;
        OPl[pe]     = f2tf(o[nf][0] * inv_lo);
        OPl[pe + 4] = f2tf(o[nf][1] * inv_lo);
        OPh[pe]     = f2tf(o[nf][2] * inv_hi);
        OPh[pe + 4] = f2tf(o[nf][3] * inv_hi);
    }
}

// ---------------------------------------------------------------------------
extern "C" void kernel_launch(void* const* d_in, const int* in_sizes, int n_in,
                              void* d_out, int out_size)
{
    const float* x  = (const float*)d_in[0];
    const float* Wq = (const float*)d_in[1];
    const float* Wk = (const float*)d_in[2];
    const float* Wv = (const float*)d_in[3];
    const float* Wo = (const float*)d_in[4];
    const int* isc  = (const int*)d_in[5];
    float* out = (float*)d_out;

    cudaFuncSetAttribute(proj_tc, cudaFuncAttributeMaxDynamicSharedMemorySize, GSMEM);
    cudaFuncSetAttribute(outproj_tc, cudaFuncAttributeMaxDynamicSharedMemorySize, GSMEM);
    cudaFuncSetAttribute(attn_tc, cudaFuncAttributeMaxDynamicSharedMemorySize, ATTN_SM);

    float* d_xt; cudaGetSymbolAddress((void**)&d_xt, g_xt);
    float* d_wot; cudaGetSymbolAddress((void**)&d_wot, g_wot);

    prep_perm<<<(MTOT * HID / 16 + 255) / 256, 256>>>(x, d_xt, MTOT * HID / 16);
    prep_perm<<<(HID * HID / 16 + 255) / 256, 256>>>(Wo, d_wot, HID * HID / 16);
    prep_wt<<<dim3(HID / 32, HD / 32, 21), dim3(32, 8)>>>(Wq, Wk, Wv);

    proj_tc<<<dim3(MTOT / 128, 21), 128, GSMEM>>>();
    compact_k<<<dim3(CPAD / 64, NH * BB), 256>>>();
    compact_vT<<<dim3(CPAD / 32, HD / 32, NH * BB), dim3(32, 8)>>>();
    attn_tc<<<dim3(TT / 64, BB, NH), 128, ATTN_SM>>>(isc);
    outproj_tc<<<dim3(MTOT / 128, HID / 128), 128, GSMEM>>>(out);
}